// round 10
// baseline (speedup 1.0000x reference)
#include <cuda_runtime.h>
#include <cuda_bf16.h>
#include <cuda_fp16.h>
#include <cstdint>

#define NROWS 16384   // B*S
#define DIM 512
#define HEAD 8
#define SLOT 112
#define HD 64
#define RADIUSF 16.0f

// ---------------- scratch (device globals) ----------------
__device__ float g_virpre[NROWS * DIM];
__device__ float g_aud[NROWS * DIM];
__device__ float g_invkn[NROWS * HEAD];
__device__ float g_gpart[NROWS * 4];
__device__ float g_cosbuf[NROWS];
__device__ float g_cpart[SLOT];
// bf16 split pairs (softmax-feeding path: 3-term accuracy)
__device__ __nv_bfloat16 g_q_h[NROWS * DIM],  g_q_l[NROWS * DIM];
__device__ __nv_bfloat16 g_v_h[NROWS * DIM],  g_v_l[NROWS * DIM];
__device__ __nv_bfloat16 g_wq_h[DIM * DIM],   g_wq_l[DIM * DIM];
__device__ __nv_bfloat16 g_wv_h[DIM * DIM],   g_wv_l[DIM * DIM];
__device__ __nv_bfloat16 g_wl_h[DIM * DIM * HEAD], g_wl_l[DIM * DIM * HEAD];
__device__ __nv_bfloat16 g_vm_h[SLOT * DIM],  g_vm_l[SLOT * DIM];
__device__ __nv_bfloat16 g_eqn_h[NROWS * DIM], g_eqn_l[NROWS * DIM];
__device__ __nv_bfloat16 g_kn_h[HEAD * SLOT * HD], g_kn_l[HEAD * SLOT * HD];
__device__ __nv_bfloat16 g_ev_h[NROWS * DIM], g_ev_l[NROWS * DIM];
__device__ __nv_bfloat16 g_vn_h[SLOT * DIM],  g_vn_l[SLOT * DIM];
// fp16 (post-softmax output path: 2-term, A hi-only, B hi+lo)
__device__ __half g_ka[NROWS * HEAD * SLOT];
__device__ __half g_va[NROWS * 128];
__device__ __half g_m2h[DIM * HEAD * SLOT], g_m2l[DIM * HEAD * SLOT];
__device__ __half g_vth[DIM * 128],         g_vtl[DIM * 128];

// ---------------- helpers ----------------
__device__ __forceinline__ uint32_t smem_u32(const void* p) {
    uint32_t a;
    asm("{ .reg .u64 t; cvta.to.shared.u64 t, %1; cvt.u32.u64 %0, t; }" : "=r"(a) : "l"(p));
    return a;
}
__device__ __forceinline__ void cp16(uint32_t dst, const void* src, int sz) {
    asm volatile("cp.async.cg.shared.global [%0], [%1], 16, %2;"
                 :: "r"(dst), "l"(src), "r"(sz));
}
__device__ __forceinline__ void cp_commit() { asm volatile("cp.async.commit_group;" ::: "memory"); }
__device__ __forceinline__ void cp_wait0()  { asm volatile("cp.async.wait_group 0;"  ::: "memory"); }

__device__ __forceinline__ void ldm4(uint32_t (&r)[4], uint32_t a) {
    asm volatile("ldmatrix.sync.aligned.m8n8.x4.shared.b16 {%0,%1,%2,%3}, [%4];"
                 : "=r"(r[0]), "=r"(r[1]), "=r"(r[2]), "=r"(r[3]) : "r"(a));
}
__device__ __forceinline__ void mma16816(float (&c)[4], const uint32_t (&a)[4],
                                         uint32_t b0, uint32_t b1) {
    asm volatile(
        "mma.sync.aligned.m16n8k16.row.col.f32.bf16.bf16.f32 "
        "{%0,%1,%2,%3}, {%4,%5,%6,%7}, {%8,%9}, {%0,%1,%2,%3};"
        : "+f"(c[0]), "+f"(c[1]), "+f"(c[2]), "+f"(c[3])
        : "r"(a[0]), "r"(a[1]), "r"(a[2]), "r"(a[3]), "r"(b0), "r"(b1));
}
__device__ __forceinline__ void mma16816h(float (&c)[4], const uint32_t (&a)[4],
                                          uint32_t b0, uint32_t b1) {
    asm volatile(
        "mma.sync.aligned.m16n8k16.row.col.f32.f16.f16.f32 "
        "{%0,%1,%2,%3}, {%4,%5,%6,%7}, {%8,%9}, {%0,%1,%2,%3};"
        : "+f"(c[0]), "+f"(c[1]), "+f"(c[2]), "+f"(c[3])
        : "r"(a[0]), "r"(a[1]), "r"(a[2]), "r"(a[3]), "r"(b0), "r"(b1));
}
__device__ __forceinline__ void wsplit(__nv_bfloat16* h, __nv_bfloat16* l, long long i, float v) {
    __nv_bfloat16 hh = __float2bfloat16_rn(v);
    h[i] = hh;
    l[i] = __float2bfloat16_rn(v - __bfloat162float(hh));
}
__device__ __forceinline__ void wsplit_f16(__half* h, __half* l, long long i, float v) {
    __half hh = __float2half_rn(v);
    h[i] = hh;
    l[i] = __float2half_rn(v - __half2float(hh));
}
__device__ __forceinline__ void spair(__nv_bfloat16* H, __nv_bfloat16* L, long long i,
                                      float a, float b) {
    __nv_bfloat16 h0 = __float2bfloat16_rn(a), h1 = __float2bfloat16_rn(b);
    *(__nv_bfloat162*)(H + i) = __halves2bfloat162(h0, h1);
    *(__nv_bfloat162*)(L + i) = __halves2bfloat162(
        __float2bfloat16_rn(a - __bfloat162float(h0)),
        __float2bfloat16_rn(b - __bfloat162float(h1)));
}
__device__ __forceinline__ void spair_f16(__half* H, __half* L, long long i,
                                          float a, float b) {
    __half h0 = __float2half_rn(a), h1 = __float2half_rn(b);
    *(__half2*)(H + i) = __halves2half2(h0, h1);
    *(__half2*)(L + i) = __halves2half2(
        __float2half_rn(a - __half2float(h0)),
        __float2half_rn(b - __half2float(h1)));
}
__device__ __forceinline__ void hpair(__half* H, long long i, float a, float b) {
    *(__half2*)(H + i) = __floats2half2_rn(a, b);
}
__device__ __forceinline__ float qred_sum(float v) {
    v += __shfl_xor_sync(0xffffffffu, v, 1);
    v += __shfl_xor_sync(0xffffffffu, v, 2);
    return v;
}
__device__ __forceinline__ float qred_max(float v) {
    v = fmaxf(v, __shfl_xor_sync(0xffffffffu, v, 1));
    v = fmaxf(v, __shfl_xor_sync(0xffffffffu, v, 2));
    return v;
}
__device__ __forceinline__ float blockReduceSum(float v, float* red) {
    int lane = threadIdx.x & 31, w = threadIdx.x >> 5;
    #pragma unroll
    for (int o = 16; o; o >>= 1) v += __shfl_down_sync(0xffffffffu, v, o);
    if (lane == 0) red[w] = v;
    __syncthreads();
    int nw = blockDim.x >> 5;
    float r = (threadIdx.x < nw) ? red[threadIdx.x] : 0.0f;
    if (w == 0) {
        #pragma unroll
        for (int o = 16; o; o >>= 1) r += __shfl_down_sync(0xffffffffu, r, o);
        if (lane == 0) red[0] = r;
    }
    __syncthreads();
    float out = red[0];
    __syncthreads();
    return out;
}

// ---------------- GEMM building blocks ----------------
#define ROWB   80
#define HALFB  10240
#define STAGEB 40960
#define GSMEM  (2 * STAGEB)

__device__ __forceinline__ void zero_acc(float (&acc)[4][4][4]) {
    #pragma unroll
    for (int i = 0; i < 4; i++)
        #pragma unroll
        for (int j = 0; j < 4; j++)
            #pragma unroll
            for (int t = 0; t < 4; t++) acc[i][j][t] = 0.0f;
}

__device__ __forceinline__ void chunk_mma3(uint32_t base, int wr, int wc, int lane,
                                           float (&acc)[4][4][4])
{
    const int rA = lane & 15, cA = lane >> 4;
    const int rB = (lane & 7) + ((lane >> 4) << 3), cB = (lane >> 3) & 1;
    #pragma unroll
    for (int k16 = 0; k16 < 2; k16++) {
        const int k2 = k16 * 2;
        uint32_t aAddr[4], bAddr[2];
        #pragma unroll
        for (int mi = 0; mi < 4; mi++)
            aAddr[mi] = base + (uint32_t)((wr * 64 + mi * 16 + rA) * ROWB + (k2 + cA) * 16);
        #pragma unroll
        for (int ni = 0; ni < 2; ni++)
            bAddr[ni] = base + 2 * HALFB +
                        (uint32_t)((wc * 32 + ni * 16 + rB) * ROWB + (k2 + cB) * 16);

        uint32_t fAh[4][4], fB[2][4];
        #pragma unroll
        for (int mi = 0; mi < 4; mi++) ldm4(fAh[mi], aAddr[mi]);
        #pragma unroll
        for (int ni = 0; ni < 2; ni++) ldm4(fB[ni], bAddr[ni]);
        #pragma unroll
        for (int mi = 0; mi < 4; mi++)
            #pragma unroll
            for (int nj = 0; nj < 4; nj++) {
                const int bi = nj >> 1, bs = (nj & 1) * 2;
                mma16816(acc[mi][nj], fAh[mi], fB[bi][bs], fB[bi][bs + 1]);
            }
        {
            uint32_t fAl[4][4];
            #pragma unroll
            for (int mi = 0; mi < 4; mi++) ldm4(fAl[mi], aAddr[mi] + HALFB);
            #pragma unroll
            for (int mi = 0; mi < 4; mi++)
                #pragma unroll
                for (int nj = 0; nj < 4; nj++) {
                    const int bi = nj >> 1, bs = (nj & 1) * 2;
                    mma16816(acc[mi][nj], fAl[mi], fB[bi][bs], fB[bi][bs + 1]);
                }
        }
        #pragma unroll
        for (int ni = 0; ni < 2; ni++) ldm4(fB[ni], bAddr[ni] + HALFB);
        #pragma unroll
        for (int mi = 0; mi < 4; mi++)
            #pragma unroll
            for (int nj = 0; nj < 4; nj++) {
                const int bi = nj >> 1, bs = (nj & 1) * 2;
                mma16816(acc[mi][nj], fAh[mi], fB[bi][bs], fB[bi][bs + 1]);
            }
    }
}

// bf16 3-term GEMM (double-buffered pipeline)
__device__ __forceinline__ void gemm_core(
    uint32_t sb, int tid,
    const __nv_bfloat16* __restrict__ Ah, const __nv_bfloat16* __restrict__ Al, int lda,
    const __nv_bfloat16* __restrict__ Bh, const __nv_bfloat16* __restrict__ Bl, int ldb,
    int K, int nvalid, float (&acc)[4][4][4])
{
    const int lane = tid & 31, wid = tid >> 5;
    const int wr = wid >> 2, wc = wid & 3;
    const int nc = K >> 5;

    auto issue = [&](int st, int c) {
        #pragma unroll
        for (int j = 0; j < 2; j++) {
            int id = tid + j * 256;
            int row = id >> 2, ch = id & 3;
            long long offa = (long long)row * lda + c * 32 + ch * 8;
            uint32_t d = sb + st * STAGEB + row * ROWB + ch * 16;
            cp16(d,         Ah + offa, 16);
            cp16(d + HALFB, Al + offa, 16);
            long long offb = (long long)row * ldb + c * 32 + ch * 8;
            int vb = (row < nvalid) ? 16 : 0;
            if (vb == 0) offb = 0;
            cp16(d + 2 * HALFB, Bh + offb, vb);
            cp16(d + 3 * HALFB, Bl + offb, vb);
        }
    };

    zero_acc(acc);
    issue(0, 0);
    cp_commit();

    for (int c = 0; c < nc; c++) {
        cp_wait0();
        __syncthreads();
        int nxt = c + 1;
        if (nxt < nc) issue(nxt & 1, nxt);
        cp_commit();
        chunk_mma3(sb + (c & 1) * STAGEB, wr, wc, lane, acc);
    }
    __syncthreads();
}

// fp16 2-term GEMM core (A hi-only, B hi+lo)
#define STAGEB2 30720
#define GSMEM2  (2 * STAGEB2)

__device__ __forceinline__ void gemm_core_f16(
    uint32_t sb, int tid,
    const __half* __restrict__ Ah, int lda,
    const __half* __restrict__ Bh, const __half* __restrict__ Bl, int ldb,
    int K, float (&acc)[4][4][4])
{
    const int lane = tid & 31, wid = tid >> 5;
    const int wr = wid >> 2, wc = wid & 3;
    const int nc = K >> 5;

    auto issue = [&](int st, int c) {
        #pragma unroll
        for (int j = 0; j < 2; j++) {
            int id = tid + j * 256;
            int row = id >> 2, ch = id & 3;
            long long offa = (long long)row * lda + c * 32 + ch * 8;
            uint32_t d = sb + st * STAGEB2 + row * ROWB + ch * 16;
            cp16(d, Ah + offa, 16);
            long long offb = (long long)row * ldb + c * 32 + ch * 8;
            cp16(d + HALFB,     Bh + offb, 16);
            cp16(d + 2 * HALFB, Bl + offb, 16);
        }
    };

    zero_acc(acc);
    issue(0, 0);
    cp_commit();

    const int rA = lane & 15, cA = lane >> 4;
    const int rB = (lane & 7) + ((lane >> 4) << 3), cB = (lane >> 3) & 1;

    for (int c = 0; c < nc; c++) {
        cp_wait0();
        __syncthreads();
        int nxt = c + 1;
        if (nxt < nc) issue(nxt & 1, nxt);
        cp_commit();
        const uint32_t base = sb + (c & 1) * STAGEB2;
        #pragma unroll
        for (int k16 = 0; k16 < 2; k16++) {
            const int k2 = k16 * 2;
            uint32_t aAddr[4], bAddr[2];
            #pragma unroll
            for (int mi = 0; mi < 4; mi++)
                aAddr[mi] = base + (uint32_t)((wr * 64 + mi * 16 + rA) * ROWB + (k2 + cA) * 16);
            #pragma unroll
            for (int ni = 0; ni < 2; ni++)
                bAddr[ni] = base + HALFB +
                            (uint32_t)((wc * 32 + ni * 16 + rB) * ROWB + (k2 + cB) * 16);

            uint32_t fAh[4][4], fB[2][4];
            #pragma unroll
            for (int mi = 0; mi < 4; mi++) ldm4(fAh[mi], aAddr[mi]);
            #pragma unroll
            for (int ni = 0; ni < 2; ni++) ldm4(fB[ni], bAddr[ni]);
            #pragma unroll
            for (int mi = 0; mi < 4; mi++)
                #pragma unroll
                for (int nj = 0; nj < 4; nj++) {
                    const int bi = nj >> 1, bs = (nj & 1) * 2;
                    mma16816h(acc[mi][nj], fAh[mi], fB[bi][bs], fB[bi][bs + 1]);
                }
            #pragma unroll
            for (int ni = 0; ni < 2; ni++) ldm4(fB[ni], bAddr[ni] + HALFB);
            #pragma unroll
            for (int mi = 0; mi < 4; mi++)
                #pragma unroll
                for (int nj = 0; nj < 4; nj++) {
                    const int bi = nj >> 1, bs = (nj & 1) * 2;
                    mma16816h(acc[mi][nj], fAh[mi], fB[bi][bs], fB[bi][bs + 1]);
                }
        }
    }
    __syncthreads();
}

// ---------------- epilogues ----------------
__device__ __forceinline__ void epi_bias(float (&acc)[4][4][4], const float* bias,
                                         int blockCol, int wc, int lane) {
    #pragma unroll
    for (int nj = 0; nj < 4; nj++) {
        const int col = blockCol + wc * 32 + nj * 8 + (lane & 3) * 2;
        float b0 = bias[col], b1 = bias[col + 1];
        #pragma unroll
        for (int mi = 0; mi < 4; mi++) {
            acc[mi][nj][0] += b0; acc[mi][nj][1] += b1;
            acc[mi][nj][2] += b0; acc[mi][nj][3] += b1;
        }
    }
}

__device__ __forceinline__ void epi_split_store(
    float (&acc)[4][4][4], __nv_bfloat16* Ch, __nv_bfloat16* Cl, int ldc,
    int blockRow, int blockCol, int ncols, int wr, int wc, int lane)
{
    #pragma unroll
    for (int mi = 0; mi < 4; mi++) {
        long long R0 = (long long)(blockRow + wr * 64 + mi * 16 + (lane >> 2)) * ldc;
        long long R1 = R0 + 8LL * ldc;
        #pragma unroll
        for (int nj = 0; nj < 4; nj++) {
            int col = blockCol + wc * 32 + nj * 8 + (lane & 3) * 2;
            if (col >= ncols) continue;
            spair(Ch, Cl, R0 + col, acc[mi][nj][0], acc[mi][nj][1]);
            spair(Ch, Cl, R1 + col, acc[mi][nj][2], acc[mi][nj][3]);
        }
    }
}

__device__ __forceinline__ void epi_split_store_f16(
    float (&acc)[4][4][4], __half* Ch, __half* Cl, int ldc,
    int blockRow, int blockCol, int ncols, int wr, int wc, int lane)
{
    #pragma unroll
    for (int mi = 0; mi < 4; mi++) {
        long long R0 = (long long)(blockRow + wr * 64 + mi * 16 + (lane >> 2)) * ldc;
        long long R1 = R0 + 8LL * ldc;
        #pragma unroll
        for (int nj = 0; nj < 4; nj++) {
            int col = blockCol + wc * 32 + nj * 8 + (lane & 3) * 2;
            if (col >= ncols) continue;
            spair_f16(Ch, Cl, R0 + col, acc[mi][nj][0], acc[mi][nj][1]);
            spair_f16(Ch, Cl, R1 + col, acc[mi][nj][2], acc[mi][nj][3]);
        }
    }
}

__device__ __forceinline__ void epi_f32_store(
    float (&acc)[4][4][4], float* Cf, int ldc,
    int blockRow, int blockCol, int wr, int wc, int lane)
{
    #pragma unroll
    for (int mi = 0; mi < 4; mi++) {
        long long R0 = (long long)(blockRow + wr * 64 + mi * 16 + (lane >> 2)) * ldc;
        long long R1 = R0 + 8LL * ldc;
        #pragma unroll
        for (int nj = 0; nj < 4; nj++) {
            int col = blockCol + wc * 32 + nj * 8 + (lane & 3) * 2;
            *(float2*)(Cf + R0 + col) = make_float2(acc[mi][nj][0], acc[mi][nj][1]);
            *(float2*)(Cf + R1 + col) = make_float2(acc[mi][nj][2], acc[mi][nj][3]);
        }
    }
}

// fused 112-slot softmax + fp16 store
__device__ __forceinline__ void softmax_store(
    float (&acc)[4][4][4], float* sred, float* ssum, const float (&scl)[4][2],
    __half* Ch, int ldc, int blockRow, bool write_pads, int wr, int wc, int lane)
{
    #pragma unroll
    for (int mi = 0; mi < 4; mi++) {
        float m0 = -1e30f, m1 = -1e30f;
        #pragma unroll
        for (int nj = 0; nj < 4; nj++) {
            const int col = wc * 32 + nj * 8 + (lane & 3) * 2;
            bool ok = col < SLOT;
            float l0 = ok ? scl[mi][0] * acc[mi][nj][0] : -1e30f;
            float l1 = ok ? scl[mi][0] * acc[mi][nj][1] : -1e30f;
            float l2 = ok ? scl[mi][1] * acc[mi][nj][2] : -1e30f;
            float l3 = ok ? scl[mi][1] * acc[mi][nj][3] : -1e30f;
            acc[mi][nj][0] = l0; acc[mi][nj][1] = l1;
            acc[mi][nj][2] = l2; acc[mi][nj][3] = l3;
            m0 = fmaxf(m0, fmaxf(l0, l1)); m1 = fmaxf(m1, fmaxf(l2, l3));
        }
        m0 = qred_max(m0); m1 = qred_max(m1);
        if ((lane & 3) == 0) {
            int r0 = wr * 64 + mi * 16 + (lane >> 2);
            sred[r0 * 4 + wc] = m0;
            sred[(r0 + 8) * 4 + wc] = m1;
        }
    }
    __syncthreads();
    #pragma unroll
    for (int mi = 0; mi < 4; mi++) {
        int r0 = wr * 64 + mi * 16 + (lane >> 2), r1 = r0 + 8;
        float M0 = fmaxf(fmaxf(sred[r0 * 4], sred[r0 * 4 + 1]),
                         fmaxf(sred[r0 * 4 + 2], sred[r0 * 4 + 3]));
        float M1 = fmaxf(fmaxf(sred[r1 * 4], sred[r1 * 4 + 1]),
                         fmaxf(sred[r1 * 4 + 2], sred[r1 * 4 + 3]));
        float s0 = 0.f, s1 = 0.f;
        #pragma unroll
        for (int nj = 0; nj < 4; nj++) {
            const int col = wc * 32 + nj * 8 + (lane & 3) * 2;
            bool ok = col < SLOT;
            float e0 = ok ? __expf(acc[mi][nj][0] - M0) : 0.f;
            float e1 = ok ? __expf(acc[mi][nj][1] - M0) : 0.f;
            float e2 = ok ? __expf(acc[mi][nj][2] - M1) : 0.f;
            float e3 = ok ? __expf(acc[mi][nj][3] - M1) : 0.f;
            acc[mi][nj][0] = e0; acc[mi][nj][1] = e1;
            acc[mi][nj][2] = e2; acc[mi][nj][3] = e3;
            s0 += e0 + e1; s1 += e2 + e3;
        }
        s0 = qred_sum(s0); s1 = qred_sum(s1);
        if ((lane & 3) == 0) {
            ssum[r0 * 4 + wc] = s0;
            ssum[r1 * 4 + wc] = s1;
        }
    }
    __syncthreads();
    #pragma unroll
    for (int mi = 0; mi < 4; mi++) {
        int r0l = wr * 64 + mi * 16 + (lane >> 2), r1l = r0l + 8;
        float i0 = 1.0f / (ssum[r0l * 4] + ssum[r0l * 4 + 1] + ssum[r0l * 4 + 2] + ssum[r0l * 4 + 3]);
        float i1 = 1.0f / (ssum[r1l * 4] + ssum[r1l * 4 + 1] + ssum[r1l * 4 + 2] + ssum[r1l * 4 + 3]);
        long long R0 = (long long)(blockRow + r0l) * ldc;
        long long R1 = (long long)(blockRow + r1l) * ldc;
        #pragma unroll
        for (int nj = 0; nj < 4; nj++) {
            const int col = wc * 32 + nj * 8 + (lane & 3) * 2;
            if (!write_pads && col >= SLOT) continue;
            hpair(Ch, R0 + col, acc[mi][nj][0] * i0, acc[mi][nj][1] * i0);
            hpair(Ch, R1 + col, acc[mi][nj][2] * i1, acc[mi][nj][3] * i1);
        }
    }
}

// ---------------- stage 1: interleaved eq/ev (y<256) + m2t (y>=256) ----------------
__global__ void __launch_bounds__(256, 2) gemm_stage1(
    const __nv_bfloat16* __restrict__ q_h, const __nv_bfloat16* __restrict__ q_l,
    const __nv_bfloat16* __restrict__ wq_h, const __nv_bfloat16* __restrict__ wq_l,
    const __nv_bfloat16* __restrict__ v_h, const __nv_bfloat16* __restrict__ v_l,
    const __nv_bfloat16* __restrict__ wv_h, const __nv_bfloat16* __restrict__ wv_l,
    const __nv_bfloat16* __restrict__ wl_h, const __nv_bfloat16* __restrict__ wl_l,
    const __nv_bfloat16* __restrict__ vm_h, const __nv_bfloat16* __restrict__ vm_l,
    __nv_bfloat16* eqn_h, __nv_bfloat16* eqn_l,
    __nv_bfloat16* ev_h, __nv_bfloat16* ev_l,
    __half* m2h, __half* m2l,
    const float* __restrict__ bq, const float* __restrict__ bv,
    float* __restrict__ invkn, float* __restrict__ gpart)
{
    extern __shared__ char smem[];
    const uint32_t sb = smem_u32(smem);
    const int tid = threadIdx.x, lane = tid & 31, wid = tid >> 5;
    const int wr = wid >> 2, wc = wid & 3;
    float acc[4][4][4];

    if (blockIdx.y >= 256) {
        // m2t: 32 units = (y-256) in [0,8) x blockIdx.x in [0,4)
        int unit = (blockIdx.y - 256) * 4 + blockIdx.x;
        int h = unit & 7, mb = unit >> 3;
        gemm_core(sb, tid, wl_h + h * 512 + (long long)mb * 128 * (HEAD * DIM),
                  wl_l + h * 512 + (long long)mb * 128 * (HEAD * DIM), HEAD * DIM,
                  vm_h, vm_l, DIM, DIM, SLOT, acc);
        epi_split_store_f16(acc, m2h + h * SLOT, m2l + h * SLOT, HEAD * SLOT,
                            mb * 128, 0, SLOT, wr, wc, lane);
        return;
    }

    const int z = blockIdx.y & 1;                 // interleave eq/ev in bid order
    const int blockRow = (blockIdx.y >> 1) * 128, blockCol = blockIdx.x * 128;
    if (z == 0)
        gemm_core(sb, tid, q_h + (long long)blockRow * DIM, q_l + (long long)blockRow * DIM, DIM,
                  wq_h + (long long)blockCol * DIM, wq_l + (long long)blockCol * DIM, DIM,
                  DIM, 128, acc);
    else
        gemm_core(sb, tid, v_h + (long long)blockRow * DIM, v_l + (long long)blockRow * DIM, DIM,
                  wv_h + (long long)blockCol * DIM, wv_l + (long long)blockCol * DIM, DIM,
                  DIM, 128, acc);

    epi_bias(acc, z == 0 ? bq : bv, blockCol, wc, lane);

    float* sred = (float*)smem;
    #pragma unroll
    for (int mi = 0; mi < 4; mi++) {
        float s0 = 0.f, s1 = 0.f;
        #pragma unroll
        for (int nj = 0; nj < 4; nj++) {
            s0 += acc[mi][nj][0] * acc[mi][nj][0] + acc[mi][nj][1] * acc[mi][nj][1];
            s1 += acc[mi][nj][2] * acc[mi][nj][2] + acc[mi][nj][3] * acc[mi][nj][3];
        }
        s0 = qred_sum(s0); s1 = qred_sum(s1);
        if ((lane & 3) == 0) {
            int r0 = wr * 64 + mi * 16 + (lane >> 2);
            sred[r0 * 4 + wc] = s0;
            sred[(r0 + 8) * 4 + wc] = s1;
        }
    }
    __syncthreads();
    if (z == 0) {
        if ((wc == 0 || wc == 2) && (lane & 3) == 0) {
            #pragma unroll
            for (int mi = 0; mi < 4; mi++)
                #pragma unroll
                for (int half = 0; half < 2; half++) {
                    int r = wr * 64 + mi * 16 + (lane >> 2) + half * 8;
                    float s = sred[r * 4 + wc] + sred[r * 4 + wc + 1];
                    invkn[(long long)(blockRow + r) * HEAD + blockIdx.x * 2 + (wc >> 1)]
                        = 1.0f / fmaxf(sqrtf(s), 1e-12f);
                }
        }
    } else {
        if (wc == 0 && (lane & 3) == 0) {
            #pragma unroll
            for (int mi = 0; mi < 4; mi++)
                #pragma unroll
                for (int half = 0; half < 2; half++) {
                    int r = wr * 64 + mi * 16 + (lane >> 2) + half * 8;
                    float s = sred[r * 4] + sred[r * 4 + 1] + sred[r * 4 + 2] + sred[r * 4 + 3];
                    gpart[(long long)(blockRow + r) * 4 + blockIdx.x] = s;
                }
        }
    }
    epi_split_store(acc, z == 0 ? eqn_h : ev_h, z == 0 ? eqn_l : ev_l, DIM,
                    blockRow, blockCol, 1 << 30, wr, wc, lane);
}

// ---------------- stage 2: interleaved vsim + 8 ksim heads (y = row*9 + slot) ----------------
#define GSMEM_SIM (2 * STAGEB + 4096)

__global__ void __launch_bounds__(256, 2) gemm_sim(
    const __nv_bfloat16* __restrict__ eqn_h, const __nv_bfloat16* __restrict__ eqn_l,
    const __nv_bfloat16* __restrict__ kn_h, const __nv_bfloat16* __restrict__ kn_l,
    const __nv_bfloat16* __restrict__ ev_h, const __nv_bfloat16* __restrict__ ev_l,
    const __nv_bfloat16* __restrict__ vn_h, const __nv_bfloat16* __restrict__ vn_l,
    __half* ka, __half* va,
    const float* __restrict__ invkn, const float* __restrict__ gpart)
{
    extern __shared__ char smem[];
    const uint32_t sb = smem_u32(smem);
    float* sredE = (float*)(smem + 2 * STAGEB);
    float* ssumE = sredE + 512;
    const int tid = threadIdx.x, lane = tid & 31, wid = tid >> 5;
    const int wr = wid >> 2, wc = wid & 3;
    const int slot = blockIdx.y % 9;              // 0 = vsim, 1..8 = ksim head
    const int blockRow = (blockIdx.y / 9) * 128;
    float acc[4][4][4];

    __half* Ch;
    int ldc;
    bool is_val = (slot == 0);
    if (is_val) {
        gemm_core(sb, tid, ev_h + (long long)blockRow * DIM, ev_l + (long long)blockRow * DIM, DIM,
                  vn_h, vn_l, DIM, DIM, SLOT, acc);
        Ch = va; ldc = 128;
    } else {
        int h = slot - 1;
        gemm_core(sb, tid, eqn_h + (long long)blockRow * DIM + h * HD,
                  eqn_l + (long long)blockRow * DIM + h * HD, DIM,
                  kn_h + (long long)h * SLOT * HD, kn_l + (long long)h * SLOT * HD, HD,
                  HD, SLOT, acc);
        Ch = ka + h * SLOT; ldc = HEAD * SLOT;
    }

    const int h = slot - 1;
    float scl[4][2];
    #pragma unroll
    for (int mi = 0; mi < 4; mi++)
        #pragma unroll
        for (int half = 0; half < 2; half++) {
            int r = blockRow + wr * 64 + mi * 16 + (lane >> 2) + half * 8;
            float iv;
            if (is_val) {
                float s4 = gpart[r * 4] + gpart[r * 4 + 1] + gpart[r * 4 + 2] + gpart[r * 4 + 3];
                iv = 1.0f / fmaxf(sqrtf(s4), 1e-12f);
            } else {
                iv = invkn[(long long)r * HEAD + h];
            }
            scl[mi][half] = RADIUSF * iv;
        }
    softmax_store(acc, sredE, ssumE, scl, Ch, ldc, blockRow, is_val, wr, wc, lane);
}

// ---------------- stage 3 (fp16 2-term): interleaved virpre / aud (y&1) ----------------
__global__ void __launch_bounds__(256, 2) gemm_out(
    const __half* __restrict__ ka, const __half* __restrict__ m2h, const __half* __restrict__ m2l,
    const __half* __restrict__ va, const __half* __restrict__ vth, const __half* __restrict__ vtl,
    float* __restrict__ virpre, float* __restrict__ aud,
    const float* __restrict__ bl)
{
    extern __shared__ char smem[];
    const uint32_t sb = smem_u32(smem);
    const int tid = threadIdx.x, lane = tid & 31, wid = tid >> 5;
    const int wr = wid >> 2, wc = wid & 3;
    const int z = blockIdx.y & 1;
    const int blockRow = (blockIdx.y >> 1) * 128, blockCol = blockIdx.x * 128;
    float acc[4][4][4];

    if (z == 0) {
        gemm_core_f16(sb, tid, ka + (long long)blockRow * (HEAD * SLOT), HEAD * SLOT,
                      m2h + (long long)blockCol * (HEAD * SLOT),
                      m2l + (long long)blockCol * (HEAD * SLOT), HEAD * SLOT,
                      HEAD * SLOT, acc);
        epi_bias(acc, bl, blockCol, wc, lane);
        epi_f32_store(acc, virpre, DIM, blockRow, blockCol, wr, wc, lane);
    } else {
        gemm_core_f16(sb, tid, va + (long long)blockRow * 128, 128,
                      vth + (long long)blockCol * 128,
                      vtl + (long long)blockCol * 128, 128,
                      128, acc);
        epi_f32_store(acc, aud, DIM, blockRow, blockCol, wr, wc, lane);
    }
}

// ---------------- mega prep ----------------
#define NB_Q  8192
#define NB_V  8192
#define NB_WQ 256
#define NB_WV 256
#define NB_WL 2048
#define NB_VM 56
#define NB_KN 112
#define NB_VN 112
#define NB_VT 256
#define NB_CP 112
#define NB_TOTAL (NB_Q+NB_V+NB_WQ+NB_WV+NB_WL+NB_VM+NB_KN+NB_VN+NB_VT+NB_CP)

__device__ __forceinline__ void do_split4(const float4* src, __nv_bfloat16* h,
                                          __nv_bfloat16* l, long long i) {
    float4 v = src[i];
    __nv_bfloat16 h0 = __float2bfloat16_rn(v.x), h1 = __float2bfloat16_rn(v.y);
    __nv_bfloat16 h2 = __float2bfloat16_rn(v.z), h3 = __float2bfloat16_rn(v.w);
    *(__nv_bfloat162*)(h + i * 4)     = __halves2bfloat162(h0, h1);
    *(__nv_bfloat162*)(h + i * 4 + 2) = __halves2bfloat162(h2, h3);
    *(__nv_bfloat162*)(l + i * 4) = __halves2bfloat162(
        __float2bfloat16_rn(v.x - __bfloat162float(h0)),
        __float2bfloat16_rn(v.y - __bfloat162float(h1)));
    *(__nv_bfloat162*)(l + i * 4 + 2) = __halves2bfloat162(
        __float2bfloat16_rn(v.z - __bfloat162float(h2)),
        __float2bfloat16_rn(v.w - __bfloat162float(h3)));
}

__global__ void mega_prep(
    const float* __restrict__ query, const float* __restrict__ value,
    const float* __restrict__ key_mem, const float* __restrict__ value_mem,
    const float* __restrict__ Wq, const float* __restrict__ Wv, const float* __restrict__ Wl,
    __nv_bfloat16* q_h, __nv_bfloat16* q_l, __nv_bfloat16* v_h, __nv_bfloat16* v_l,
    __nv_bfloat16* wq_h, __nv_bfloat16* wq_l, __nv_bfloat16* wv_h, __nv_bfloat16* wv_l,
    __nv_bfloat16* wl_h, __nv_bfloat16* wl_l, __nv_bfloat16* vm_h, __nv_bfloat16* vm_l,
    __nv_bfloat16* kn_h, __nv_bfloat16* kn_l, __nv_bfloat16* vn_h, __nv_bfloat16* vn_l,
    __half* vth, __half* vtl, float* cpart)
{
    __shared__ float sh[544];
    int b = blockIdx.x, tid = threadIdx.x;

    if (b < NB_Q) { do_split4((const float4*)query, q_h, q_l, (long long)b * 256 + tid); return; }
    b -= NB_Q;
    if (b < NB_V) { do_split4((const float4*)value, v_h, v_l, (long long)b * 256 + tid); return; }
    b -= NB_V;
    if (b < NB_WQ) { do_split4((const float4*)Wq, wq_h, wq_l, (long long)b * 256 + tid); return; }
    b -= NB_WQ;
    if (b < NB_WV) { do_split4((const float4*)Wv, wv_h, wv_l, (long long)b * 256 + tid); return; }
    b -= NB_WV;
    if (b < NB_WL) { do_split4((const float4*)Wl, wl_h, wl_l, (long long)b * 256 + tid); return; }
    b -= NB_WL;
    if (b < NB_VM) { do_split4((const float4*)value_mem, vm_h, vm_l, (long long)b * 256 + tid); return; }
    b -= NB_VM;
    if (b < NB_KN) {
        int seg = b * 8 + (tid >> 5), lane = tid & 31;
        long long base = (long long)seg * 64;
        float a = key_mem[base + lane], c = key_mem[base + lane + 32];
        float s = a * a + c * c;
        #pragma unroll
        for (int o = 16; o; o >>= 1) s += __shfl_xor_sync(0xffffffffu, s, o);
        float inv = 1.0f / fmaxf(sqrtf(s), 1e-12f);
        wsplit(kn_h, kn_l, base + lane, a * inv);
        wsplit(kn_h, kn_l, base + lane + 32, c * inv);
        return;
    }
    b -= NB_KN;
    if (b < NB_VN) {
        long long r = b;
        float a = value_mem[r * DIM + tid], c = value_mem[r * DIM + tid + 256];
        float s = blockReduceSum(a * a + c * c, sh);
        float inv = 1.0f / fmaxf(sqrtf(s), 1e-12f);
        wsplit(vn_h, vn_l, r * DIM + tid, a * inv);
        wsplit(vn_h, vn_l, r * DIM + tid + 256, c * inv);
        return;
    }
    b -= NB_VN;
    if (b < NB_VT) {
        int idx = b * 256 + tid;
        int j = idx >> 7, s = idx & 127;
        float v = (s < SLOT) ? value_mem[(long long)s * DIM + j] : 0.0f;
        wsplit_f16(vth, vtl, idx, v);
        return;
    }
    b -= NB_VT;
    {
        int i = b;
        float* vi = sh;
        float* red = sh + 512;
        for (int c = tid; c < DIM; c += 256) vi[c] = value_mem[(long long)i * DIM + c];
        __syncthreads();
        float s = 0.f;
        for (int c = tid; c < DIM; c += 256) s += vi[c] * vi[c];
        s = blockReduceSum(s, red);
        float ni = fmaxf(sqrtf(s), 1e-12f);
        int w = tid >> 5, lane = tid & 31;
        float acc = 0.f;
        for (int j = w; j < SLOT; j += 8) {
            float d = 0.f, jj = 0.f;
            for (int c = lane; c < DIM; c += 32) {
                float vj = value_mem[(long long)j * DIM + c];
                d += vi[c] * vj; jj += vj * vj;
            }
            #pragma unroll
            for (int o = 16; o; o >>= 1) {
                d += __shfl_down_sync(0xffffffffu, d, o);
                jj += __shfl_down_sync(0xffffffffu, jj, o);
            }
            if (lane == 0) {
                float nj = fmaxf(sqrtf(jj), 1e-12f);
                acc += fabsf(((i == j) ? 1.0f : 0.0f) - d / (ni * nj));
            }
        }
        acc = blockReduceSum(acc, red);
        if (tid == 0) cpart[i] = acc;
    }
}

// ---------------- fused te+tr layernorm ----------------
__global__ void fuse_tetr(const float* __restrict__ virpre, const float* __restrict__ aud,
                          const float* __restrict__ query, const float* __restrict__ value,
                          const float* __restrict__ g1, const float* __restrict__ b1,
                          const float* __restrict__ g2, const float* __restrict__ b2,
                          const float* __restrict__ g3, const float* __restrict__ b3,
                          float* __restrict__ out_te, float* __restrict__ out_tr,
                          float* __restrict__ cosbuf)
{
    __shared__ float red[32];
    bool is_tr = blockIdx.x >= NROWS;
    long long r = is_tr ? (blockIdx.x - NROWS) : blockIdx.x;
    const float* src = (is_tr ? aud : virpre) + r * DIM;
    const float* q = query + r * DIM;
    const float* gx = is_tr ? g3 : g2;
    const float* bx = is_tr ? b3 : b2;
    float* o = (is_tr ? out_tr : out_te) + r * DIM;

    float x[4], qv[4];
    float s = 0.f, s2 = 0.f;
    #pragma unroll
    for (int i = 0; i < 4; i++) {
        int c = threadIdx.x + 128 * i;
        x[i] = src[c]; qv[i] = q[c];
        s += x[i]; s2 += x[i] * x[i];
    }
    s  = blockReduceSum(s,  red);
    s2 = blockReduceSum(s2, red);
    if (is_tr) {
        const float* v = value + r * DIM;
        float sav = 0.f, svv = 0.f;
        #pragma unroll
        for (int i = 0; i < 4; i++) {
            int c = threadIdx.x + 128 * i;
            float vv = v[c];
            sav += x[i] * vv; svv += vv * vv;
        }
        sav = blockReduceSum(sav, red);
        svv = blockReduceSum(svv, red);
        if (threadIdx.x == 0) {
            float cosv = sav / fmaxf(sqrtf(s2) * sqrtf(svv), 1e-8f);
            cosbuf[r] = fabsf(1.0f - cosv);
        }
    }
    float mu = s * (1.0f / DIM);
    float var = s2 * (1.0f / DIM) - mu * mu;
    float inv = rsqrtf(var + 1e-5f);
    float t[4]; float ts = 0.f, ts2 = 0.f;
    #pragma unroll
    for (int i = 0; i < 4; i++) {
        int c = threadIdx.x + 128 * i;
        float ln = (x[i] - mu) * inv * gx[c] + bx[c];
        t[i] = qv[i] + ln; ts += t[i]; ts2 += t[i] * t[i];
    }
    ts  = blockReduceSum(ts,  red);
    ts2 = blockReduceSum(ts2, red);
    mu = ts * (1.0f / DIM);
    var = ts2 * (1.0f / DIM) - mu * mu;
    inv = rsqrtf(var + 1e-5f);
    #pragma unroll
    for (int i = 0; i < 4; i++) {
        int c = threadIdx.x + 128 * i;
        o[c] = (t[i] - mu) * inv * g1[c] + b1[c];
    }
}

// ---------------- final reductions ----------------
__global__ void final_reduce(const float* __restrict__ cosbuf, const float* __restrict__ cpart,
                             float* __restrict__ recon, float* __restrict__ contr)
{
    __shared__ float red[32];
    int b = blockIdx.x;
    if (b < 32) {
        float s = 0.0f;
        for (int i = threadIdx.x; i < 512; i += blockDim.x) s += cosbuf[b * 512 + i];
        s = blockReduceSum(s, red);
        if (threadIdx.x == 0) recon[b] = s;
    } else {
        float s = 0.0f;
        for (int i = threadIdx.x; i < SLOT; i += blockDim.x) s += cpart[i];
        s = blockReduceSum(s, red);
        if (threadIdx.x == 0) contr[0] = 0.5f * s;
    }
}

// ---------------- launch ----------------
#define SYM(p, s) cudaGetSymbolAddress((void**)&p, s)

extern "C" void kernel_launch(void* const* d_in, const int* in_sizes, int n_in,
                              void* d_out, int out_size)
{
    const float* query     = (const float*)d_in[0];
    const float* value     = (const float*)d_in[1];
    const float* key_mem   = (const float*)d_in[2];
    const float* value_mem = (const float*)d_in[3];
    const float* Wq = (const float*)d_in[4];
    const float* bq = (const float*)d_in[5];
    const float* Wv = (const float*)d_in[6];
    const float* bv = (const float*)d_in[7];
    const float* Wl = (const float*)d_in[8];
    const float* bl = (const float*)d_in[9];
    const float* g1 = (const float*)d_in[10];
    const float* b1 = (const float*)d_in[11];
    const float* g2 = (const float*)d_in[12];
    const float* b2 = (const float*)d_in[13];
    const float* g3 = (const float*)d_in[14];
    const float* b3 = (const float*)d_in[15];

    float* out        = (float*)d_out;
    float* out_te     = out;
    float* out_tr     = out + (long long)NROWS * DIM;
    float* out_recon  = out + 2ll * NROWS * DIM;
    float* out_contr  = out_recon + 32;

    float *p_virpre, *p_aud, *p_invkn, *p_gpart, *p_cos, *p_cpart;
    SYM(p_virpre, g_virpre); SYM(p_aud, g_aud);
    SYM(p_invkn, g_invkn); SYM(p_gpart, g_gpart);
    SYM(p_cos, g_cosbuf); SYM(p_cpart, g_cpart);

    __nv_bfloat16 *q_h, *q_l, *v_h, *v_l, *wq_h, *wq_l, *wv_h, *wv_l, *wl_h, *wl_l;
    __nv_bfloat16 *vm_h, *vm_l, *eqn_h, *eqn_l, *kn_h, *kn_l;
    __nv_bfloat16 *ev_h, *ev_l, *vn_h, *vn_l;
    __half *ka, *va, *m2h, *m2l, *vth, *vtl;
    SYM(q_h, g_q_h); SYM(q_l, g_q_l); SYM(v_h, g_v_h); SYM(v_l, g_v_l);
    SYM(wq_h, g_wq_h); SYM(wq_l, g_wq_l); SYM(wv_h, g_wv_h); SYM(wv_l, g_wv_l);
    SYM(wl_h, g_wl_h); SYM(wl_l, g_wl_l); SYM(vm_h, g_vm_h); SYM(vm_l, g_vm_l);
    SYM(eqn_h, g_eqn_h); SYM(eqn_l, g_eqn_l); SYM(kn_h, g_kn_h); SYM(kn_l, g_kn_l);
    SYM(ev_h, g_ev_h); SYM(ev_l, g_ev_l); SYM(vn_h, g_vn_h); SYM(vn_l, g_vn_l);
    SYM(ka, g_ka); SYM(va, g_va); SYM(m2h, g_m2h); SYM(m2l, g_m2l);
    SYM(vth, g_vth); SYM(vtl, g_vtl);

    cudaFuncSetAttribute(gemm_stage1, cudaFuncAttributeMaxDynamicSharedMemorySize, GSMEM);
    cudaFuncSetAttribute(gemm_sim,    cudaFuncAttributeMaxDynamicSharedMemorySize, GSMEM_SIM);
    cudaFuncSetAttribute(gemm_out,    cudaFuncAttributeMaxDynamicSharedMemorySize, GSMEM2);

    // 0: all prep (splits, norms, contrastive partials)
    mega_prep<<<NB_TOTAL, 256>>>(query, value, key_mem, value_mem, Wq, Wv, Wl,
                                 q_h, q_l, v_h, v_l, wq_h, wq_l, wv_h, wv_l,
                                 wl_h, wl_l, vm_h, vm_l, kn_h, kn_l, vn_h, vn_l,
                                 vth, vtl, p_cpart);

    // 1: interleaved eq/ev (y<256) + m2t (y>=256, 32 units)
    gemm_stage1<<<dim3(4, 264, 1), 256, GSMEM>>>(
        q_h, q_l, wq_h, wq_l, v_h, v_l, wv_h, wv_l, wl_h, wl_l, vm_h, vm_l,
        eqn_h, eqn_l, ev_h, ev_l, m2h, m2l, bq, bv, p_invkn, p_gpart);

    // 2: interleaved vsim + ksim heads (y = row*9 + slot), fused softmaxes -> fp16
    gemm_sim<<<dim3(1, 128 * 9, 1), 256, GSMEM_SIM>>>(
        eqn_h, eqn_l, kn_h, kn_l, ev_h, ev_l, vn_h, vn_l,
        ka, va, p_invkn, p_gpart);

    // 3: interleaved virpre (K=896) / aud (K=128) — fp16 2-term
    gemm_out<<<dim3(4, 256, 1), 256, GSMEM2>>>(
        ka, m2h, m2l, va, vth, vtl, p_virpre, p_aud, bl);

    // 4: fused te + tr double-layernorm (+cos)
    fuse_tetr<<<2 * NROWS, 128>>>(p_virpre, p_aud, query, value,
                                  g1, b1, g2, b2, g3, b3, out_te, out_tr, p_cos);

    // 5: recon per-batch sums + contrastive final
    final_reduce<<<33, 128>>>(p_cos, p_cpart, out_recon, out_contr);
}

// round 11
// speedup vs baseline: 1.1135x; 1.1135x over previous
#include <cuda_runtime.h>
#include <cuda_bf16.h>
#include <cuda_fp16.h>
#include <cstdint>

#define NROWS 16384   // B*S
#define DIM 512
#define HEAD 8
#define SLOT 112
#define HD 64
#define RADIUSF 16.0f

// ---------------- scratch (device globals) ----------------
__device__ float g_virpre[NROWS * DIM];
__device__ float g_aud[NROWS * DIM];
__device__ float g_invkn[NROWS * HEAD];
__device__ float g_gpart[NROWS * 4];
__device__ float g_cosbuf[NROWS];
__device__ float g_cpart[SLOT];
// bf16 split pairs (softmax-feeding path: 3-term accuracy)
__device__ __nv_bfloat16 g_q_h[NROWS * DIM],  g_q_l[NROWS * DIM];
__device__ __nv_bfloat16 g_v_h[NROWS * DIM],  g_v_l[NROWS * DIM];
__device__ __nv_bfloat16 g_wq_h[DIM * DIM],   g_wq_l[DIM * DIM];
__device__ __nv_bfloat16 g_wv_h[DIM * DIM],   g_wv_l[DIM * DIM];
__device__ __nv_bfloat16 g_wl_h[DIM * DIM * HEAD], g_wl_l[DIM * DIM * HEAD];
__device__ __nv_bfloat16 g_vm_h[SLOT * DIM],  g_vm_l[SLOT * DIM];
__device__ __nv_bfloat16 g_eqn_h[NROWS * DIM], g_eqn_l[NROWS * DIM];
__device__ __nv_bfloat16 g_kn_h[HEAD * SLOT * HD], g_kn_l[HEAD * SLOT * HD];
__device__ __nv_bfloat16 g_ev_h[NROWS * DIM], g_ev_l[NROWS * DIM];
__device__ __nv_bfloat16 g_vn_h[SLOT * DIM],  g_vn_l[SLOT * DIM];
// fp16 (post-softmax output path: 2-term, A hi-only, B hi+lo)
__device__ __half g_ka[NROWS * HEAD * SLOT];
__device__ __half g_va[NROWS * 128];
__device__ __half g_m2h[DIM * HEAD * SLOT], g_m2l[DIM * HEAD * SLOT];
__device__ __half g_vth[DIM * 128],         g_vtl[DIM * 128];

// ---------------- helpers ----------------
__device__ __forceinline__ uint32_t smem_u32(const void* p) {
    uint32_t a;
    asm("{ .reg .u64 t; cvta.to.shared.u64 t, %1; cvt.u32.u64 %0, t; }" : "=r"(a) : "l"(p));
    return a;
}
__device__ __forceinline__ void cp16(uint32_t dst, const void* src, int sz) {
    asm volatile("cp.async.cg.shared.global [%0], [%1], 16, %2;"
                 :: "r"(dst), "l"(src), "r"(sz));
}
__device__ __forceinline__ void cp_commit() { asm volatile("cp.async.commit_group;" ::: "memory"); }
__device__ __forceinline__ void cp_wait0()  { asm volatile("cp.async.wait_group 0;"  ::: "memory"); }
__device__ __forceinline__ void cp_wait1()  { asm volatile("cp.async.wait_group 1;"  ::: "memory"); }

__device__ __forceinline__ void ldm4(uint32_t (&r)[4], uint32_t a) {
    asm volatile("ldmatrix.sync.aligned.m8n8.x4.shared.b16 {%0,%1,%2,%3}, [%4];"
                 : "=r"(r[0]), "=r"(r[1]), "=r"(r[2]), "=r"(r[3]) : "r"(a));
}
__device__ __forceinline__ void mma16816(float (&c)[4], const uint32_t (&a)[4],
                                         uint32_t b0, uint32_t b1) {
    asm volatile(
        "mma.sync.aligned.m16n8k16.row.col.f32.bf16.bf16.f32 "
        "{%0,%1,%2,%3}, {%4,%5,%6,%7}, {%8,%9}, {%0,%1,%2,%3};"
        : "+f"(c[0]), "+f"(c[1]), "+f"(c[2]), "+f"(c[3])
        : "r"(a[0]), "r"(a[1]), "r"(a[2]), "r"(a[3]), "r"(b0), "r"(b1));
}
__device__ __forceinline__ void mma16816h(float (&c)[4], const uint32_t (&a)[4],
                                          uint32_t b0, uint32_t b1) {
    asm volatile(
        "mma.sync.aligned.m16n8k16.row.col.f32.f16.f16.f32 "
        "{%0,%1,%2,%3}, {%4,%5,%6,%7}, {%8,%9}, {%0,%1,%2,%3};"
        : "+f"(c[0]), "+f"(c[1]), "+f"(c[2]), "+f"(c[3])
        : "r"(a[0]), "r"(a[1]), "r"(a[2]), "r"(a[3]), "r"(b0), "r"(b1));
}
__device__ __forceinline__ void wsplit(__nv_bfloat16* h, __nv_bfloat16* l, long long i, float v) {
    __nv_bfloat16 hh = __float2bfloat16_rn(v);
    h[i] = hh;
    l[i] = __float2bfloat16_rn(v - __bfloat162float(hh));
}
__device__ __forceinline__ void wsplit_f16(__half* h, __half* l, long long i, float v) {
    __half hh = __float2half_rn(v);
    h[i] = hh;
    l[i] = __float2half_rn(v - __half2float(hh));
}
__device__ __forceinline__ void spair(__nv_bfloat16* H, __nv_bfloat16* L, long long i,
                                      float a, float b) {
    __nv_bfloat16 h0 = __float2bfloat16_rn(a), h1 = __float2bfloat16_rn(b);
    *(__nv_bfloat162*)(H + i) = __halves2bfloat162(h0, h1);
    *(__nv_bfloat162*)(L + i) = __halves2bfloat162(
        __float2bfloat16_rn(a - __bfloat162float(h0)),
        __float2bfloat16_rn(b - __bfloat162float(h1)));
}
__device__ __forceinline__ void spair_f16(__half* H, __half* L, long long i,
                                          float a, float b) {
    __half h0 = __float2half_rn(a), h1 = __float2half_rn(b);
    *(__half2*)(H + i) = __halves2half2(h0, h1);
    *(__half2*)(L + i) = __halves2half2(
        __float2half_rn(a - __half2float(h0)),
        __float2half_rn(b - __half2float(h1)));
}
__device__ __forceinline__ void hpair(__half* H, long long i, float a, float b) {
    *(__half2*)(H + i) = __floats2half2_rn(a, b);
}
__device__ __forceinline__ float qred_sum(float v) {
    v += __shfl_xor_sync(0xffffffffu, v, 1);
    v += __shfl_xor_sync(0xffffffffu, v, 2);
    return v;
}
__device__ __forceinline__ float qred_max(float v) {
    v = fmaxf(v, __shfl_xor_sync(0xffffffffu, v, 1));
    v = fmaxf(v, __shfl_xor_sync(0xffffffffu, v, 2));
    return v;
}
__device__ __forceinline__ float blockReduceSum(float v, float* red) {
    int lane = threadIdx.x & 31, w = threadIdx.x >> 5;
    #pragma unroll
    for (int o = 16; o; o >>= 1) v += __shfl_down_sync(0xffffffffu, v, o);
    if (lane == 0) red[w] = v;
    __syncthreads();
    int nw = blockDim.x >> 5;
    float r = (threadIdx.x < nw) ? red[threadIdx.x] : 0.0f;
    if (w == 0) {
        #pragma unroll
        for (int o = 16; o; o >>= 1) r += __shfl_down_sync(0xffffffffu, r, o);
        if (lane == 0) red[0] = r;
    }
    __syncthreads();
    float out = red[0];
    __syncthreads();
    return out;
}

// ---------------- GEMM building blocks ----------------
#define ROWB   80
#define HALFB  10240
#define STAGEB 40960
#define GSMEM     (2 * STAGEB)
#define GSMEM_SIM (2 * STAGEB + 4096)

__device__ __forceinline__ void zero_acc(float (&acc)[4][4][4]) {
    #pragma unroll
    for (int i = 0; i < 4; i++)
        #pragma unroll
        for (int j = 0; j < 4; j++)
            #pragma unroll
            for (int t = 0; t < 4; t++) acc[i][j][t] = 0.0f;
}

__device__ __forceinline__ void chunk_mma3(uint32_t base, int wr, int wc, int lane,
                                           float (&acc)[4][4][4])
{
    const int rA = lane & 15, cA = lane >> 4;
    const int rB = (lane & 7) + ((lane >> 4) << 3), cB = (lane >> 3) & 1;
    #pragma unroll
    for (int k16 = 0; k16 < 2; k16++) {
        const int k2 = k16 * 2;
        uint32_t aAddr[4], bAddr[2];
        #pragma unroll
        for (int mi = 0; mi < 4; mi++)
            aAddr[mi] = base + (uint32_t)((wr * 64 + mi * 16 + rA) * ROWB + (k2 + cA) * 16);
        #pragma unroll
        for (int ni = 0; ni < 2; ni++)
            bAddr[ni] = base + 2 * HALFB +
                        (uint32_t)((wc * 32 + ni * 16 + rB) * ROWB + (k2 + cB) * 16);

        uint32_t fAh[4][4], fB[2][4];
        #pragma unroll
        for (int mi = 0; mi < 4; mi++) ldm4(fAh[mi], aAddr[mi]);
        #pragma unroll
        for (int ni = 0; ni < 2; ni++) ldm4(fB[ni], bAddr[ni]);
        #pragma unroll
        for (int mi = 0; mi < 4; mi++)
            #pragma unroll
            for (int nj = 0; nj < 4; nj++) {
                const int bi = nj >> 1, bs = (nj & 1) * 2;
                mma16816(acc[mi][nj], fAh[mi], fB[bi][bs], fB[bi][bs + 1]);
            }
        {
            uint32_t fAl[4][4];
            #pragma unroll
            for (int mi = 0; mi < 4; mi++) ldm4(fAl[mi], aAddr[mi] + HALFB);
            #pragma unroll
            for (int mi = 0; mi < 4; mi++)
                #pragma unroll
                for (int nj = 0; nj < 4; nj++) {
                    const int bi = nj >> 1, bs = (nj & 1) * 2;
                    mma16816(acc[mi][nj], fAl[mi], fB[bi][bs], fB[bi][bs + 1]);
                }
        }
        #pragma unroll
        for (int ni = 0; ni < 2; ni++) ldm4(fB[ni], bAddr[ni] + HALFB);
        #pragma unroll
        for (int mi = 0; mi < 4; mi++)
            #pragma unroll
            for (int nj = 0; nj < 4; nj++) {
                const int bi = nj >> 1, bs = (nj & 1) * 2;
                mma16816(acc[mi][nj], fAh[mi], fB[bi][bs], fB[bi][bs + 1]);
            }
    }
}

// bf16 3-term GEMM (double-buffered pipeline)
__device__ __forceinline__ void gemm_core(
    uint32_t sb, int tid,
    const __nv_bfloat16* __restrict__ Ah, const __nv_bfloat16* __restrict__ Al, int lda,
    const __nv_bfloat16* __restrict__ Bh, const __nv_bfloat16* __restrict__ Bl, int ldb,
    int K, int nvalid, float (&acc)[4][4][4])
{
    const int lane = tid & 31, wid = tid >> 5;
    const int wr = wid >> 2, wc = wid & 3;
    const int nc = K >> 5;

    auto issue = [&](int st, int c) {
        #pragma unroll
        for (int j = 0; j < 2; j++) {
            int id = tid + j * 256;
            int row = id >> 2, ch = id & 3;
            long long offa = (long long)row * lda + c * 32 + ch * 8;
            uint32_t d = sb + st * STAGEB + row * ROWB + ch * 16;
            cp16(d,         Ah + offa, 16);
            cp16(d + HALFB, Al + offa, 16);
            long long offb = (long long)row * ldb + c * 32 + ch * 8;
            int vb = (row < nvalid) ? 16 : 0;
            if (vb == 0) offb = 0;
            cp16(d + 2 * HALFB, Bh + offb, vb);
            cp16(d + 3 * HALFB, Bl + offb, vb);
        }
    };

    zero_acc(acc);
    issue(0, 0);
    cp_commit();

    for (int c = 0; c < nc; c++) {
        cp_wait0();
        __syncthreads();
        int nxt = c + 1;
        if (nxt < nc) issue(nxt & 1, nxt);
        cp_commit();
        chunk_mma3(sb + (c & 1) * STAGEB, wr, wc, lane, acc);
    }
    __syncthreads();
}

// fp16 2-term GEMM core (A hi-only, B hi+lo), 3-stage pipeline
#define STAGEB2 30720
#define GSMEM2  (3 * STAGEB2)

__device__ __forceinline__ void gemm_core_f16(
    uint32_t sb, int tid,
    const __half* __restrict__ Ah, int lda,
    const __half* __restrict__ Bh, const __half* __restrict__ Bl, int ldb,
    int K, float (&acc)[4][4][4])
{
    const int lane = tid & 31, wid = tid >> 5;
    const int wr = wid >> 2, wc = wid & 3;
    const int nc = K >> 5;

    auto issue = [&](int st, int c) {
        #pragma unroll
        for (int j = 0; j < 2; j++) {
            int id = tid + j * 256;
            int row = id >> 2, ch = id & 3;
            long long offa = (long long)row * lda + c * 32 + ch * 8;
            uint32_t d = sb + st * STAGEB2 + row * ROWB + ch * 16;
            cp16(d, Ah + offa, 16);
            long long offb = (long long)row * ldb + c * 32 + ch * 8;
            cp16(d + HALFB,     Bh + offb, 16);
            cp16(d + 2 * HALFB, Bl + offb, 16);
        }
    };

    zero_acc(acc);
    issue(0, 0); cp_commit();
    if (nc > 1) issue(1, 1);
    cp_commit();

    const int rA = lane & 15, cA = lane >> 4;
    const int rB = (lane & 7) + ((lane >> 4) << 3), cB = (lane >> 3) & 1;

    for (int c = 0; c < nc; c++) {
        cp_wait1();
        __syncthreads();
        int nxt = c + 2;
        if (nxt < nc) issue(nxt % 3, nxt);   // stage (c+2)%3: consumed at iter c-1, all warps past it
        cp_commit();
        const uint32_t base = sb + (c % 3) * STAGEB2;
        #pragma unroll
        for (int k16 = 0; k16 < 2; k16++) {
            const int k2 = k16 * 2;
            uint32_t aAddr[4], bAddr[2];
            #pragma unroll
            for (int mi = 0; mi < 4; mi++)
                aAddr[mi] = base + (uint32_t)((wr * 64 + mi * 16 + rA) * ROWB + (k2 + cA) * 16);
            #pragma unroll
            for (int ni = 0; ni < 2; ni++)
                bAddr[ni] = base + HALFB +
                            (uint32_t)((wc * 32 + ni * 16 + rB) * ROWB + (k2 + cB) * 16);

            uint32_t fAh[4][4], fB[2][4];
            #pragma unroll
            for (int mi = 0; mi < 4; mi++) ldm4(fAh[mi], aAddr[mi]);
            #pragma unroll
            for (int ni = 0; ni < 2; ni++) ldm4(fB[ni], bAddr[ni]);
            #pragma unroll
            for (int mi = 0; mi < 4; mi++)
                #pragma unroll
                for (int nj = 0; nj < 4; nj++) {
                    const int bi = nj >> 1, bs = (nj & 1) * 2;
                    mma16816h(acc[mi][nj], fAh[mi], fB[bi][bs], fB[bi][bs + 1]);
                }
            #pragma unroll
            for (int ni = 0; ni < 2; ni++) ldm4(fB[ni], bAddr[ni] + HALFB);
            #pragma unroll
            for (int mi = 0; mi < 4; mi++)
                #pragma unroll
                for (int nj = 0; nj < 4; nj++) {
                    const int bi = nj >> 1, bs = (nj & 1) * 2;
                    mma16816h(acc[mi][nj], fAh[mi], fB[bi][bs], fB[bi][bs + 1]);
                }
        }
    }
    cp_wait0();
    __syncthreads();
}

// ---------------- epilogues ----------------
__device__ __forceinline__ void epi_bias(float (&acc)[4][4][4], const float* bias,
                                         int blockCol, int wc, int lane) {
    #pragma unroll
    for (int nj = 0; nj < 4; nj++) {
        const int col = blockCol + wc * 32 + nj * 8 + (lane & 3) * 2;
        float b0 = bias[col], b1 = bias[col + 1];
        #pragma unroll
        for (int mi = 0; mi < 4; mi++) {
            acc[mi][nj][0] += b0; acc[mi][nj][1] += b1;
            acc[mi][nj][2] += b0; acc[mi][nj][3] += b1;
        }
    }
}

__device__ __forceinline__ void epi_split_store(
    float (&acc)[4][4][4], __nv_bfloat16* Ch, __nv_bfloat16* Cl, int ldc,
    int blockRow, int blockCol, int ncols, int wr, int wc, int lane)
{
    #pragma unroll
    for (int mi = 0; mi < 4; mi++) {
        long long R0 = (long long)(blockRow + wr * 64 + mi * 16 + (lane >> 2)) * ldc;
        long long R1 = R0 + 8LL * ldc;
        #pragma unroll
        for (int nj = 0; nj < 4; nj++) {
            int col = blockCol + wc * 32 + nj * 8 + (lane & 3) * 2;
            if (col >= ncols) continue;
            spair(Ch, Cl, R0 + col, acc[mi][nj][0], acc[mi][nj][1]);
            spair(Ch, Cl, R1 + col, acc[mi][nj][2], acc[mi][nj][3]);
        }
    }
}

__device__ __forceinline__ void epi_split_store_f16(
    float (&acc)[4][4][4], __half* Ch, __half* Cl, int ldc,
    int blockRow, int blockCol, int ncols, int wr, int wc, int lane)
{
    #pragma unroll
    for (int mi = 0; mi < 4; mi++) {
        long long R0 = (long long)(blockRow + wr * 64 + mi * 16 + (lane >> 2)) * ldc;
        long long R1 = R0 + 8LL * ldc;
        #pragma unroll
        for (int nj = 0; nj < 4; nj++) {
            int col = blockCol + wc * 32 + nj * 8 + (lane & 3) * 2;
            if (col >= ncols) continue;
            spair_f16(Ch, Cl, R0 + col, acc[mi][nj][0], acc[mi][nj][1]);
            spair_f16(Ch, Cl, R1 + col, acc[mi][nj][2], acc[mi][nj][3]);
        }
    }
}

__device__ __forceinline__ void epi_f32_store(
    float (&acc)[4][4][4], float* Cf, int ldc,
    int blockRow, int blockCol, int wr, int wc, int lane)
{
    #pragma unroll
    for (int mi = 0; mi < 4; mi++) {
        long long R0 = (long long)(blockRow + wr * 64 + mi * 16 + (lane >> 2)) * ldc;
        long long R1 = R0 + 8LL * ldc;
        #pragma unroll
        for (int nj = 0; nj < 4; nj++) {
            int col = blockCol + wc * 32 + nj * 8 + (lane & 3) * 2;
            *(float2*)(Cf + R0 + col) = make_float2(acc[mi][nj][0], acc[mi][nj][1]);
            *(float2*)(Cf + R1 + col) = make_float2(acc[mi][nj][2], acc[mi][nj][3]);
        }
    }
}

// fused 112-slot softmax + fp16 store
__device__ __forceinline__ void softmax_store(
    float (&acc)[4][4][4], float* sred, float* ssum, const float (&scl)[4][2],
    __half* Ch, int ldc, int blockRow, bool write_pads, int wr, int wc, int lane)
{
    #pragma unroll
    for (int mi = 0; mi < 4; mi++) {
        float m0 = -1e30f, m1 = -1e30f;
        #pragma unroll
        for (int nj = 0; nj < 4; nj++) {
            const int col = wc * 32 + nj * 8 + (lane & 3) * 2;
            bool ok = col < SLOT;
            float l0 = ok ? scl[mi][0] * acc[mi][nj][0] : -1e30f;
            float l1 = ok ? scl[mi][0] * acc[mi][nj][1] : -1e30f;
            float l2 = ok ? scl[mi][1] * acc[mi][nj][2] : -1e30f;
            float l3 = ok ? scl[mi][1] * acc[mi][nj][3] : -1e30f;
            acc[mi][nj][0] = l0; acc[mi][nj][1] = l1;
            acc[mi][nj][2] = l2; acc[mi][nj][3] = l3;
            m0 = fmaxf(m0, fmaxf(l0, l1)); m1 = fmaxf(m1, fmaxf(l2, l3));
        }
        m0 = qred_max(m0); m1 = qred_max(m1);
        if ((lane & 3) == 0) {
            int r0 = wr * 64 + mi * 16 + (lane >> 2);
            sred[r0 * 4 + wc] = m0;
            sred[(r0 + 8) * 4 + wc] = m1;
        }
    }
    __syncthreads();
    #pragma unroll
    for (int mi = 0; mi < 4; mi++) {
        int r0 = wr * 64 + mi * 16 + (lane >> 2), r1 = r0 + 8;
        float M0 = fmaxf(fmaxf(sred[r0 * 4], sred[r0 * 4 + 1]),
                         fmaxf(sred[r0 * 4 + 2], sred[r0 * 4 + 3]));
        float M1 = fmaxf(fmaxf(sred[r1 * 4], sred[r1 * 4 + 1]),
                         fmaxf(sred[r1 * 4 + 2], sred[r1 * 4 + 3]));
        float s0 = 0.f, s1 = 0.f;
        #pragma unroll
        for (int nj = 0; nj < 4; nj++) {
            const int col = wc * 32 + nj * 8 + (lane & 3) * 2;
            bool ok = col < SLOT;
            float e0 = ok ? __expf(acc[mi][nj][0] - M0) : 0.f;
            float e1 = ok ? __expf(acc[mi][nj][1] - M0) : 0.f;
            float e2 = ok ? __expf(acc[mi][nj][2] - M1) : 0.f;
            float e3 = ok ? __expf(acc[mi][nj][3] - M1) : 0.f;
            acc[mi][nj][0] = e0; acc[mi][nj][1] = e1;
            acc[mi][nj][2] = e2; acc[mi][nj][3] = e3;
            s0 += e0 + e1; s1 += e2 + e3;
        }
        s0 = qred_sum(s0); s1 = qred_sum(s1);
        if ((lane & 3) == 0) {
            ssum[r0 * 4 + wc] = s0;
            ssum[r1 * 4 + wc] = s1;
        }
    }
    __syncthreads();
    #pragma unroll
    for (int mi = 0; mi < 4; mi++) {
        int r0l = wr * 64 + mi * 16 + (lane >> 2), r1l = r0l + 8;
        float i0 = 1.0f / (ssum[r0l * 4] + ssum[r0l * 4 + 1] + ssum[r0l * 4 + 2] + ssum[r0l * 4 + 3]);
        float i1 = 1.0f / (ssum[r1l * 4] + ssum[r1l * 4 + 1] + ssum[r1l * 4 + 2] + ssum[r1l * 4 + 3]);
        long long R0 = (long long)(blockRow + r0l) * ldc;
        long long R1 = (long long)(blockRow + r1l) * ldc;
        #pragma unroll
        for (int nj = 0; nj < 4; nj++) {
            const int col = wc * 32 + nj * 8 + (lane & 3) * 2;
            if (!write_pads && col >= SLOT) continue;
            hpair(Ch, R0 + col, acc[mi][nj][0] * i0, acc[mi][nj][1] * i0);
            hpair(Ch, R1 + col, acc[mi][nj][2] * i1, acc[mi][nj][3] * i1);
        }
    }
}

// ---------------- stage 1: eq (z=0), ev (z=1), m2t (z=2) ----------------
__global__ void __launch_bounds__(256, 2) gemm_stage1(
    const __nv_bfloat16* __restrict__ q_h, const __nv_bfloat16* __restrict__ q_l,
    const __nv_bfloat16* __restrict__ wq_h, const __nv_bfloat16* __restrict__ wq_l,
    const __nv_bfloat16* __restrict__ v_h, const __nv_bfloat16* __restrict__ v_l,
    const __nv_bfloat16* __restrict__ wv_h, const __nv_bfloat16* __restrict__ wv_l,
    const __nv_bfloat16* __restrict__ wl_h, const __nv_bfloat16* __restrict__ wl_l,
    const __nv_bfloat16* __restrict__ vm_h, const __nv_bfloat16* __restrict__ vm_l,
    __nv_bfloat16* eqn_h, __nv_bfloat16* eqn_l,
    __nv_bfloat16* ev_h, __nv_bfloat16* ev_l,
    __half* m2h, __half* m2l,
    const float* __restrict__ bq, const float* __restrict__ bv,
    float* __restrict__ invkn, float* __restrict__ gpart)
{
    extern __shared__ char smem[];
    const uint32_t sb = smem_u32(smem);
    const int tid = threadIdx.x, lane = tid & 31, wid = tid >> 5;
    const int wr = wid >> 2, wc = wid & 3;
    const int z = blockIdx.z;
    float acc[4][4][4];

    if (z == 2) {
        if (blockIdx.x != 0 || blockIdx.y >= 32) return;
        int h = blockIdx.y & 7, mb = blockIdx.y >> 3;
        gemm_core(sb, tid, wl_h + h * 512 + (long long)mb * 128 * (HEAD * DIM),
                  wl_l + h * 512 + (long long)mb * 128 * (HEAD * DIM), HEAD * DIM,
                  vm_h, vm_l, DIM, DIM, SLOT, acc);
        epi_split_store_f16(acc, m2h + h * SLOT, m2l + h * SLOT, HEAD * SLOT,
                            mb * 128, 0, SLOT, wr, wc, lane);
        return;
    }

    const int blockRow = blockIdx.y * 128, blockCol = blockIdx.x * 128;
    if (z == 0)
        gemm_core(sb, tid, q_h + (long long)blockRow * DIM, q_l + (long long)blockRow * DIM, DIM,
                  wq_h + (long long)blockCol * DIM, wq_l + (long long)blockCol * DIM, DIM,
                  DIM, 128, acc);
    else
        gemm_core(sb, tid, v_h + (long long)blockRow * DIM, v_l + (long long)blockRow * DIM, DIM,
                  wv_h + (long long)blockCol * DIM, wv_l + (long long)blockCol * DIM, DIM,
                  DIM, 128, acc);

    epi_bias(acc, z == 0 ? bq : bv, blockCol, wc, lane);

    float* sred = (float*)smem;
    #pragma unroll
    for (int mi = 0; mi < 4; mi++) {
        float s0 = 0.f, s1 = 0.f;
        #pragma unroll
        for (int nj = 0; nj < 4; nj++) {
            s0 += acc[mi][nj][0] * acc[mi][nj][0] + acc[mi][nj][1] * acc[mi][nj][1];
            s1 += acc[mi][nj][2] * acc[mi][nj][2] + acc[mi][nj][3] * acc[mi][nj][3];
        }
        s0 = qred_sum(s0); s1 = qred_sum(s1);
        if ((lane & 3) == 0) {
            int r0 = wr * 64 + mi * 16 + (lane >> 2);
            sred[r0 * 4 + wc] = s0;
            sred[(r0 + 8) * 4 + wc] = s1;
        }
    }
    __syncthreads();
    if (z == 0) {
        if ((wc == 0 || wc == 2) && (lane & 3) == 0) {
            #pragma unroll
            for (int mi = 0; mi < 4; mi++)
                #pragma unroll
                for (int half = 0; half < 2; half++) {
                    int r = wr * 64 + mi * 16 + (lane >> 2) + half * 8;
                    float s = sred[r * 4 + wc] + sred[r * 4 + wc + 1];
                    invkn[(long long)(blockRow + r) * HEAD + blockIdx.x * 2 + (wc >> 1)]
                        = 1.0f / fmaxf(sqrtf(s), 1e-12f);
                }
        }
    } else {
        if (wc == 0 && (lane & 3) == 0) {
            #pragma unroll
            for (int mi = 0; mi < 4; mi++)
                #pragma unroll
                for (int half = 0; half < 2; half++) {
                    int r = wr * 64 + mi * 16 + (lane >> 2) + half * 8;
                    float s = sred[r * 4] + sred[r * 4 + 1] + sred[r * 4 + 2] + sred[r * 4 + 3];
                    gpart[(long long)(blockRow + r) * 4 + blockIdx.x] = s;
                }
        }
    }
    epi_split_store(acc, z == 0 ? eqn_h : ev_h, z == 0 ? eqn_l : ev_l, DIM,
                    blockRow, blockCol, 1 << 30, wr, wc, lane);
}

// ---------------- stage 2: vsim (z=0) + ksim heads (z=1..8) ----------------
__global__ void __launch_bounds__(256, 2) gemm_sim(
    const __nv_bfloat16* __restrict__ eqn_h, const __nv_bfloat16* __restrict__ eqn_l,
    const __nv_bfloat16* __restrict__ kn_h, const __nv_bfloat16* __restrict__ kn_l,
    const __nv_bfloat16* __restrict__ ev_h, const __nv_bfloat16* __restrict__ ev_l,
    const __nv_bfloat16* __restrict__ vn_h, const __nv_bfloat16* __restrict__ vn_l,
    __half* ka, __half* va,
    const float* __restrict__ invkn, const float* __restrict__ gpart)
{
    extern __shared__ char smem[];
    const uint32_t sb = smem_u32(smem);
    float* sredE = (float*)(smem + 2 * STAGEB);
    float* ssumE = sredE + 512;
    const int tid = threadIdx.x, lane = tid & 31, wid = tid >> 5;
    const int wr = wid >> 2, wc = wid & 3;
    const int z = blockIdx.z;
    const int blockRow = blockIdx.y * 128;
    float acc[4][4][4];

    __half* Ch;
    int ldc;
    bool is_val = (z == 0);
    if (is_val) {
        gemm_core(sb, tid, ev_h + (long long)blockRow * DIM, ev_l + (long long)blockRow * DIM, DIM,
                  vn_h, vn_l, DIM, DIM, SLOT, acc);
        Ch = va; ldc = 128;
    } else {
        int h = z - 1;
        gemm_core(sb, tid, eqn_h + (long long)blockRow * DIM + h * HD,
                  eqn_l + (long long)blockRow * DIM + h * HD, DIM,
                  kn_h + (long long)h * SLOT * HD, kn_l + (long long)h * SLOT * HD, HD,
                  HD, SLOT, acc);
        Ch = ka + h * SLOT; ldc = HEAD * SLOT;
    }

    const int h = z - 1;
    float scl[4][2];
    #pragma unroll
    for (int mi = 0; mi < 4; mi++)
        #pragma unroll
        for (int half = 0; half < 2; half++) {
            int r = blockRow + wr * 64 + mi * 16 + (lane >> 2) + half * 8;
            float iv;
            if (is_val) {
                float s4 = gpart[r * 4] + gpart[r * 4 + 1] + gpart[r * 4 + 2] + gpart[r * 4 + 3];
                iv = 1.0f / fmaxf(sqrtf(s4), 1e-12f);
            } else {
                iv = invkn[(long long)r * HEAD + h];
            }
            scl[mi][half] = RADIUSF * iv;
        }
    softmax_store(acc, sredE, ssumE, scl, Ch, ldc, blockRow, is_val, wr, wc, lane);
}

// ---------------- stage 3 (fp16 2-term): virpre (z=0, K=896) + aud (z=1, K=128) ----------------
__global__ void __launch_bounds__(256, 2) gemm_out(
    const __half* __restrict__ ka, const __half* __restrict__ m2h, const __half* __restrict__ m2l,
    const __half* __restrict__ va, const __half* __restrict__ vth, const __half* __restrict__ vtl,
    float* __restrict__ virpre, float* __restrict__ aud,
    const float* __restrict__ bl)
{
    extern __shared__ char smem[];
    const uint32_t sb = smem_u32(smem);
    const int tid = threadIdx.x, lane = tid & 31, wid = tid >> 5;
    const int wr = wid >> 2, wc = wid & 3;
    const int z = blockIdx.z;
    const int blockRow = blockIdx.y * 128, blockCol = blockIdx.x * 128;
    float acc[4][4][4];

    if (z == 0) {
        gemm_core_f16(sb, tid, ka + (long long)blockRow * (HEAD * SLOT), HEAD * SLOT,
                      m2h + (long long)blockCol * (HEAD * SLOT),
                      m2l + (long long)blockCol * (HEAD * SLOT), HEAD * SLOT,
                      HEAD * SLOT, acc);
        epi_bias(acc, bl, blockCol, wc, lane);
        epi_f32_store(acc, virpre, DIM, blockRow, blockCol, wr, wc, lane);
    } else {
        gemm_core_f16(sb, tid, va + (long long)blockRow * 128, 128,
                      vth + (long long)blockCol * 128,
                      vtl + (long long)blockCol * 128, 128,
                      128, acc);
        epi_f32_store(acc, aud, DIM, blockRow, blockCol, wr, wc, lane);
    }
}

// ---------------- mega prep (coarsened: 2 float4/thread in split sections) ----------------
#define NB_Q  4096
#define NB_V  4096
#define NB_WQ 128
#define NB_WV 128
#define NB_WL 1024
#define NB_VM 28
#define NB_KN 112
#define NB_VN 112
#define NB_VT 256
#define NB_CP 112
#define NB_TOTAL (NB_Q+NB_V+NB_WQ+NB_WV+NB_WL+NB_VM+NB_KN+NB_VN+NB_VT+NB_CP)

__device__ __forceinline__ void do_split4(const float4* src, __nv_bfloat16* h,
                                          __nv_bfloat16* l, long long i) {
    float4 v = src[i];
    __nv_bfloat16 h0 = __float2bfloat16_rn(v.x), h1 = __float2bfloat16_rn(v.y);
    __nv_bfloat16 h2 = __float2bfloat16_rn(v.z), h3 = __float2bfloat16_rn(v.w);
    *(__nv_bfloat162*)(h + i * 4)     = __halves2bfloat162(h0, h1);
    *(__nv_bfloat162*)(h + i * 4 + 2) = __halves2bfloat162(h2, h3);
    *(__nv_bfloat162*)(l + i * 4) = __halves2bfloat162(
        __float2bfloat16_rn(v.x - __bfloat162float(h0)),
        __float2bfloat16_rn(v.y - __bfloat162float(h1)));
    *(__nv_bfloat162*)(l + i * 4 + 2) = __halves2bfloat162(
        __float2bfloat16_rn(v.z - __bfloat162float(h2)),
        __float2bfloat16_rn(v.w - __bfloat162float(h3)));
}
__device__ __forceinline__ void do_split8(const float4* src, __nv_bfloat16* h,
                                          __nv_bfloat16* l, long long b, int tid) {
    do_split4(src, h, l, b * 512 + tid);
    do_split4(src, h, l, b * 512 + 256 + tid);
}

__global__ void mega_prep(
    const float* __restrict__ query, const float* __restrict__ value,
    const float* __restrict__ key_mem, const float* __restrict__ value_mem,
    const float* __restrict__ Wq, const float* __restrict__ Wv, const float* __restrict__ Wl,
    __nv_bfloat16* q_h, __nv_bfloat16* q_l, __nv_bfloat16* v_h, __nv_bfloat16* v_l,
    __nv_bfloat16* wq_h, __nv_bfloat16* wq_l, __nv_bfloat16* wv_h, __nv_bfloat16* wv_l,
    __nv_bfloat16* wl_h, __nv_bfloat16* wl_l, __nv_bfloat16* vm_h, __nv_bfloat16* vm_l,
    __nv_bfloat16* kn_h, __nv_bfloat16* kn_l, __nv_bfloat16* vn_h, __nv_bfloat16* vn_l,
    __half* vth, __half* vtl, float* cpart)
{
    __shared__ float sh[544];
    int b = blockIdx.x, tid = threadIdx.x;

    if (b < NB_Q) { do_split8((const float4*)query, q_h, q_l, b, tid); return; }
    b -= NB_Q;
    if (b < NB_V) { do_split8((const float4*)value, v_h, v_l, b, tid); return; }
    b -= NB_V;
    if (b < NB_WQ) { do_split8((const float4*)Wq, wq_h, wq_l, b, tid); return; }
    b -= NB_WQ;
    if (b < NB_WV) { do_split8((const float4*)Wv, wv_h, wv_l, b, tid); return; }
    b -= NB_WV;
    if (b < NB_WL) { do_split8((const float4*)Wl, wl_h, wl_l, b, tid); return; }
    b -= NB_WL;
    if (b < NB_VM) { do_split8((const float4*)value_mem, vm_h, vm_l, b, tid); return; }
    b -= NB_VM;
    if (b < NB_KN) {
        int seg = b * 8 + (tid >> 5), lane = tid & 31;
        long long base = (long long)seg * 64;
        float a = key_mem[base + lane], c = key_mem[base + lane + 32];
        float s = a * a + c * c;
        #pragma unroll
        for (int o = 16; o; o >>= 1) s += __shfl_xor_sync(0xffffffffu, s, o);
        float inv = 1.0f / fmaxf(sqrtf(s), 1e-12f);
        wsplit(kn_h, kn_l, base + lane, a * inv);
        wsplit(kn_h, kn_l, base + lane + 32, c * inv);
        return;
    }
    b -= NB_KN;
    if (b < NB_VN) {
        long long r = b;
        float a = value_mem[r * DIM + tid], c = value_mem[r * DIM + tid + 256];
        float s = blockReduceSum(a * a + c * c, sh);
        float inv = 1.0f / fmaxf(sqrtf(s), 1e-12f);
        wsplit(vn_h, vn_l, r * DIM + tid, a * inv);
        wsplit(vn_h, vn_l, r * DIM + tid + 256, c * inv);
        return;
    }
    b -= NB_VN;
    if (b < NB_VT) {
        int idx = b * 256 + tid;
        int j = idx >> 7, s = idx & 127;
        float v = (s < SLOT) ? value_mem[(long long)s * DIM + j] : 0.0f;
        wsplit_f16(vth, vtl, idx, v);
        return;
    }
    b -= NB_VT;
    {
        int i = b;
        float* vi = sh;
        float* red = sh + 512;
        for (int c = tid; c < DIM; c += 256) vi[c] = value_mem[(long long)i * DIM + c];
        __syncthreads();
        float s = 0.f;
        for (int c = tid; c < DIM; c += 256) s += vi[c] * vi[c];
        s = blockReduceSum(s, red);
        float ni = fmaxf(sqrtf(s), 1e-12f);
        int w = tid >> 5, lane = tid & 31;
        float acc = 0.f;
        for (int j = w; j < SLOT; j += 8) {
            float d = 0.f, jj = 0.f;
            for (int c = lane; c < DIM; c += 32) {
                float vj = value_mem[(long long)j * DIM + c];
                d += vi[c] * vj; jj += vj * vj;
            }
            #pragma unroll
            for (int o = 16; o; o >>= 1) {
                d += __shfl_down_sync(0xffffffffu, d, o);
                jj += __shfl_down_sync(0xffffffffu, jj, o);
            }
            if (lane == 0) {
                float nj = fmaxf(sqrtf(jj), 1e-12f);
                acc += fabsf(((i == j) ? 1.0f : 0.0f) - d / (ni * nj));
            }
        }
        acc = blockReduceSum(acc, red);
        if (tid == 0) cpart[i] = acc;
    }
}

// ---------------- fused te+tr layernorm ----------------
__global__ void fuse_tetr(const float* __restrict__ virpre, const float* __restrict__ aud,
                          const float* __restrict__ query, const float* __restrict__ value,
                          const float* __restrict__ g1, const float* __restrict__ b1,
                          const float* __restrict__ g2, const float* __restrict__ b2,
                          const float* __restrict__ g3, const float* __restrict__ b3,
                          float* __restrict__ out_te, float* __restrict__ out_tr,
                          float* __restrict__ cosbuf)
{
    __shared__ float red[32];
    bool is_tr = blockIdx.x >= NROWS;
    long long r = is_tr ? (blockIdx.x - NROWS) : blockIdx.x;
    const float* src = (is_tr ? aud : virpre) + r * DIM;
    const float* q = query + r * DIM;
    const float* gx = is_tr ? g3 : g2;
    const float* bx = is_tr ? b3 : b2;
    float* o = (is_tr ? out_tr : out_te) + r * DIM;

    float x[4], qv[4];
    float s = 0.f, s2 = 0.f;
    #pragma unroll
    for (int i = 0; i < 4; i++) {
        int c = threadIdx.x + 128 * i;
        x[i] = src[c]; qv[i] = q[c];
        s += x[i]; s2 += x[i] * x[i];
    }
    s  = blockReduceSum(s,  red);
    s2 = blockReduceSum(s2, red);
    if (is_tr) {
        const float* v = value + r * DIM;
        float sav = 0.f, svv = 0.f;
        #pragma unroll
        for (int i = 0; i < 4; i++) {
            int c = threadIdx.x + 128 * i;
            float vv = v[c];
            sav += x[i] * vv; svv += vv * vv;
        }
        sav = blockReduceSum(sav, red);
        svv = blockReduceSum(svv, red);
        if (threadIdx.x == 0) {
            float cosv = sav / fmaxf(sqrtf(s2) * sqrtf(svv), 1e-8f);
            cosbuf[r] = fabsf(1.0f - cosv);
        }
    }
    float mu = s * (1.0f / DIM);
    float var = s2 * (1.0f / DIM) - mu * mu;
    float inv = rsqrtf(var + 1e-5f);
    float t[4]; float ts = 0.f, ts2 = 0.f;
    #pragma unroll
    for (int i = 0; i < 4; i++) {
        int c = threadIdx.x + 128 * i;
        float ln = (x[i] - mu) * inv * gx[c] + bx[c];
        t[i] = qv[i] + ln; ts += t[i]; ts2 += t[i] * t[i];
    }
    ts  = blockReduceSum(ts,  red);
    ts2 = blockReduceSum(ts2, red);
    mu = ts * (1.0f / DIM);
    var = ts2 * (1.0f / DIM) - mu * mu;
    inv = rsqrtf(var + 1e-5f);
    #pragma unroll
    for (int i = 0; i < 4; i++) {
        int c = threadIdx.x + 128 * i;
        o[c] = (t[i] - mu) * inv * g1[c] + b1[c];
    }
}

// ---------------- final reductions ----------------
__global__ void final_reduce(const float* __restrict__ cosbuf, const float* __restrict__ cpart,
                             float* __restrict__ recon, float* __restrict__ contr)
{
    __shared__ float red[32];
    int b = blockIdx.x;
    if (b < 32) {
        float s = 0.0f;
        for (int i = threadIdx.x; i < 512; i += blockDim.x) s += cosbuf[b * 512 + i];
        s = blockReduceSum(s, red);
        if (threadIdx.x == 0) recon[b] = s;
    } else {
        float s = 0.0f;
        for (int i = threadIdx.x; i < SLOT; i += blockDim.x) s += cpart[i];
        s = blockReduceSum(s, red);
        if (threadIdx.x == 0) contr[0] = 0.5f * s;
    }
}

// ---------------- launch ----------------
#define SYM(p, s) cudaGetSymbolAddress((void**)&p, s)

extern "C" void kernel_launch(void* const* d_in, const int* in_sizes, int n_in,
                              void* d_out, int out_size)
{
    const float* query     = (const float*)d_in[0];
    const float* value     = (const float*)d_in[1];
    const float* key_mem   = (const float*)d_in[2];
    const float* value_mem = (const float*)d_in[3];
    const float* Wq = (const float*)d_in[4];
    const float* bq = (const float*)d_in[5];
    const float* Wv = (const float*)d_in[6];
    const float* bv = (const float*)d_in[7];
    const float* Wl = (const float*)d_in[8];
    const float* bl = (const float*)d_in[9];
    const float* g1 = (const float*)d_in[10];
    const float* b1 = (const float*)d_in[11];
    const float* g2 = (const float*)d_in[12];
    const float* b2 = (const float*)d_in[13];
    const float* g3 = (const float*)d_in[14];
    const float* b3 = (const float*)d_in[15];

    float* out        = (float*)d_out;
    float* out_te     = out;
    float* out_tr     = out + (long long)NROWS * DIM;
    float* out_recon  = out + 2ll * NROWS * DIM;
    float* out_contr  = out_recon + 32;

    float *p_virpre, *p_aud, *p_invkn, *p_gpart, *p_cos, *p_cpart;
    SYM(p_virpre, g_virpre); SYM(p_aud, g_aud);
    SYM(p_invkn, g_invkn); SYM(p_gpart, g_gpart);
    SYM(p_cos, g_cosbuf); SYM(p_cpart, g_cpart);

    __nv_bfloat16 *q_h, *q_l, *v_h, *v_l, *wq_h, *wq_l, *wv_h, *wv_l, *wl_h, *wl_l;
    __nv_bfloat16 *vm_h, *vm_l, *eqn_h, *eqn_l, *kn_h, *kn_l;
    __nv_bfloat16 *ev_h, *ev_l, *vn_h, *vn_l;
    __half *ka, *va, *m2h, *m2l, *vth, *vtl;
    SYM(q_h, g_q_h); SYM(q_l, g_q_l); SYM(v_h, g_v_h); SYM(v_l, g_v_l);
    SYM(wq_h, g_wq_h); SYM(wq_l, g_wq_l); SYM(wv_h, g_wv_h); SYM(wv_l, g_wv_l);
    SYM(wl_h, g_wl_h); SYM(wl_l, g_wl_l); SYM(vm_h, g_vm_h); SYM(vm_l, g_vm_l);
    SYM(eqn_h, g_eqn_h); SYM(eqn_l, g_eqn_l); SYM(kn_h, g_kn_h); SYM(kn_l, g_kn_l);
    SYM(ev_h, g_ev_h); SYM(ev_l, g_ev_l); SYM(vn_h, g_vn_h); SYM(vn_l, g_vn_l);
    SYM(ka, g_ka); SYM(va, g_va); SYM(m2h, g_m2h); SYM(m2l, g_m2l);
    SYM(vth, g_vth); SYM(vtl, g_vtl);

    cudaFuncSetAttribute(gemm_stage1, cudaFuncAttributeMaxDynamicSharedMemorySize, GSMEM);
    cudaFuncSetAttribute(gemm_sim,    cudaFuncAttributeMaxDynamicSharedMemorySize, GSMEM_SIM);
    cudaFuncSetAttribute(gemm_out,    cudaFuncAttributeMaxDynamicSharedMemorySize, GSMEM2);

    // 0: all prep (splits, norms, contrastive partials)
    mega_prep<<<NB_TOTAL, 256>>>(query, value, key_mem, value_mem, Wq, Wv, Wl,
                                 q_h, q_l, v_h, v_l, wq_h, wq_l, wv_h, wv_l,
                                 wl_h, wl_l, vm_h, vm_l, kn_h, kn_l, vn_h, vn_l,
                                 vth, vtl, p_cpart);

    // 1: eq (z=0) + ev (z=1) + m2t (z=2, fp16 split out)
    gemm_stage1<<<dim3(4, 128, 3), 256, GSMEM>>>(
        q_h, q_l, wq_h, wq_l, v_h, v_l, wv_h, wv_l, wl_h, wl_l, vm_h, vm_l,
        eqn_h, eqn_l, ev_h, ev_l, m2h, m2l, bq, bv, p_invkn, p_gpart);

    // 2: vsim (z=0) + ksim heads (z=1..8), fused softmaxes -> fp16
    gemm_sim<<<dim3(1, 128, 9), 256, GSMEM_SIM>>>(
        eqn_h, eqn_l, kn_h, kn_l, ev_h, ev_l, vn_h, vn_l,
        ka, va, p_invkn, p_gpart);

    // 3: virpre (z=0, K=896) + aud (z=1, K=128) — fp16 2-term, 3-stage pipeline
    gemm_out<<<dim3(4, 128, 2), 256, GSMEM2>>>(
        ka, m2h, m2l, va, vth, vtl, p_virpre, p_aud, bl);

    // 4: fused te + tr double-layernorm (+cos)
    fuse_tetr<<<2 * NROWS, 128>>>(p_virpre, p_aud, query, value,
                                  g1, b1, g2, b2, g3, b3, out_te, out_tr, p_cos);

    // 5: recon per-batch sums + contrastive final
    final_reduce<<<33, 128>>>(p_cos, p_cpart, out_recon, out_contr);
}

// round 12
// speedup vs baseline: 1.1569x; 1.0389x over previous
#include <cuda_runtime.h>
#include <cuda_bf16.h>
#include <cuda_fp16.h>
#include <cstdint>

#define NROWS 16384   // B*S
#define DIM 512
#define HEAD 8
#define SLOT 112
#define HD 64
#define RADIUSF 16.0f

// ---------------- scratch (device globals) ----------------
__device__ float g_virpre[NROWS * DIM];
__device__ float g_aud[NROWS * DIM];
__device__ float g_invkn[NROWS * HEAD];
__device__ float g_gpart[NROWS * 4];
__device__ float g_cosbuf[NROWS];
__device__ float g_cpart[SLOT];
// bf16 split pairs (softmax-feeding path: 3-term accuracy)
__device__ __nv_bfloat16 g_q_h[NROWS * DIM],  g_q_l[NROWS * DIM];
__device__ __nv_bfloat16 g_v_h[NROWS * DIM],  g_v_l[NROWS * DIM];
__device__ __nv_bfloat16 g_wq_h[DIM * DIM],   g_wq_l[DIM * DIM];
__device__ __nv_bfloat16 g_wv_h[DIM * DIM],   g_wv_l[DIM * DIM];
__device__ __nv_bfloat16 g_wl_h[DIM * DIM * HEAD], g_wl_l[DIM * DIM * HEAD];
__device__ __nv_bfloat16 g_vm_h[SLOT * DIM],  g_vm_l[SLOT * DIM];
__device__ __nv_bfloat16 g_eqn_h[NROWS * DIM], g_eqn_l[NROWS * DIM];
__device__ __nv_bfloat16 g_kn_h[HEAD * SLOT * HD], g_kn_l[HEAD * SLOT * HD];
__device__ __nv_bfloat16 g_ev_h[NROWS * DIM], g_ev_l[NROWS * DIM];
__device__ __nv_bfloat16 g_vn_h[SLOT * DIM],  g_vn_l[SLOT * DIM];
// fp16 (post-softmax output path: 2-term, A hi-only, B hi+lo)
__device__ __half g_ka[NROWS * HEAD * SLOT];
__device__ __half g_va[NROWS * 128];
__device__ __half g_m2h[DIM * HEAD * SLOT], g_m2l[DIM * HEAD * SLOT];
__device__ __half g_vth[DIM * 128],         g_vtl[DIM * 128];

// ---------------- helpers ----------------
__device__ __forceinline__ uint32_t smem_u32(const void* p) {
    uint32_t a;
    asm("{ .reg .u64 t; cvta.to.shared.u64 t, %1; cvt.u32.u64 %0, t; }" : "=r"(a) : "l"(p));
    return a;
}
__device__ __forceinline__ void cp16(uint32_t dst, const void* src, int sz) {
    asm volatile("cp.async.cg.shared.global [%0], [%1], 16, %2;"
                 :: "r"(dst), "l"(src), "r"(sz));
}
__device__ __forceinline__ void cp_commit() { asm volatile("cp.async.commit_group;" ::: "memory"); }
__device__ __forceinline__ void cp_wait0()  { asm volatile("cp.async.wait_group 0;"  ::: "memory"); }

__device__ __forceinline__ void ldm4(uint32_t (&r)[4], uint32_t a) {
    asm volatile("ldmatrix.sync.aligned.m8n8.x4.shared.b16 {%0,%1,%2,%3}, [%4];"
                 : "=r"(r[0]), "=r"(r[1]), "=r"(r[2]), "=r"(r[3]) : "r"(a));
}
__device__ __forceinline__ void mma16816(float (&c)[4], const uint32_t (&a)[4],
                                         uint32_t b0, uint32_t b1) {
    asm volatile(
        "mma.sync.aligned.m16n8k16.row.col.f32.bf16.bf16.f32 "
        "{%0,%1,%2,%3}, {%4,%5,%6,%7}, {%8,%9}, {%0,%1,%2,%3};"
        : "+f"(c[0]), "+f"(c[1]), "+f"(c[2]), "+f"(c[3])
        : "r"(a[0]), "r"(a[1]), "r"(a[2]), "r"(a[3]), "r"(b0), "r"(b1));
}
__device__ __forceinline__ void mma16816h(float (&c)[4], const uint32_t (&a)[4],
                                          uint32_t b0, uint32_t b1) {
    asm volatile(
        "mma.sync.aligned.m16n8k16.row.col.f32.f16.f16.f32 "
        "{%0,%1,%2,%3}, {%4,%5,%6,%7}, {%8,%9}, {%0,%1,%2,%3};"
        : "+f"(c[0]), "+f"(c[1]), "+f"(c[2]), "+f"(c[3])
        : "r"(a[0]), "r"(a[1]), "r"(a[2]), "r"(a[3]), "r"(b0), "r"(b1));
}
__device__ __forceinline__ void wsplit(__nv_bfloat16* h, __nv_bfloat16* l, long long i, float v) {
    __nv_bfloat16 hh = __float2bfloat16_rn(v);
    h[i] = hh;
    l[i] = __float2bfloat16_rn(v - __bfloat162float(hh));
}
__device__ __forceinline__ void wsplit_f16(__half* h, __half* l, long long i, float v) {
    __half hh = __float2half_rn(v);
    h[i] = hh;
    l[i] = __float2half_rn(v - __half2float(hh));
}
__device__ __forceinline__ void spair(__nv_bfloat16* H, __nv_bfloat16* L, long long i,
                                      float a, float b) {
    __nv_bfloat16 h0 = __float2bfloat16_rn(a), h1 = __float2bfloat16_rn(b);
    *(__nv_bfloat162*)(H + i) = __halves2bfloat162(h0, h1);
    *(__nv_bfloat162*)(L + i) = __halves2bfloat162(
        __float2bfloat16_rn(a - __bfloat162float(h0)),
        __float2bfloat16_rn(b - __bfloat162float(h1)));
}
__device__ __forceinline__ void spair_f16(__half* H, __half* L, long long i,
                                          float a, float b) {
    __half h0 = __float2half_rn(a), h1 = __float2half_rn(b);
    *(__half2*)(H + i) = __halves2half2(h0, h1);
    *(__half2*)(L + i) = __halves2half2(
        __float2half_rn(a - __half2float(h0)),
        __float2half_rn(b - __half2float(h1)));
}
__device__ __forceinline__ void hpair(__half* H, long long i, float a, float b) {
    *(__half2*)(H + i) = __floats2half2_rn(a, b);
}
__device__ __forceinline__ float qred_sum(float v) {
    v += __shfl_xor_sync(0xffffffffu, v, 1);
    v += __shfl_xor_sync(0xffffffffu, v, 2);
    return v;
}
__device__ __forceinline__ float qred_max(float v) {
    v = fmaxf(v, __shfl_xor_sync(0xffffffffu, v, 1));
    v = fmaxf(v, __shfl_xor_sync(0xffffffffu, v, 2));
    return v;
}
__device__ __forceinline__ float blockReduceSum(float v, float* red) {
    int lane = threadIdx.x & 31, w = threadIdx.x >> 5;
    #pragma unroll
    for (int o = 16; o; o >>= 1) v += __shfl_down_sync(0xffffffffu, v, o);
    if (lane == 0) red[w] = v;
    __syncthreads();
    int nw = blockDim.x >> 5;
    float r = (threadIdx.x < nw) ? red[threadIdx.x] : 0.0f;
    if (w == 0) {
        #pragma unroll
        for (int o = 16; o; o >>= 1) r += __shfl_down_sync(0xffffffffu, r, o);
        if (lane == 0) red[0] = r;
    }
    __syncthreads();
    float out = red[0];
    __syncthreads();
    return out;
}
// dual-value single-sync block reduction for 128-thread blocks (4 warps).
// red must point at 8 floats, distinct per call site (rotating regions).
__device__ __forceinline__ void blockReduceSum2_128(float& a, float& b, float* red) {
    int lane = threadIdx.x & 31, w = threadIdx.x >> 5;
    #pragma unroll
    for (int o = 16; o; o >>= 1) {
        a += __shfl_down_sync(0xffffffffu, a, o);
        b += __shfl_down_sync(0xffffffffu, b, o);
    }
    if (lane == 0) { red[w] = a; red[4 + w] = b; }
    __syncthreads();
    a = red[0] + red[1] + red[2] + red[3];
    b = red[4] + red[5] + red[6] + red[7];
}

// ---------------- GEMM building blocks ----------------
#define ROWB   80
#define HALFB  10240
#define STAGEB 40960
#define GSMEM     (2 * STAGEB)
#define GSMEM_SIM (2 * STAGEB + 4096)

__device__ __forceinline__ void zero_acc(float (&acc)[4][4][4]) {
    #pragma unroll
    for (int i = 0; i < 4; i++)
        #pragma unroll
        for (int j = 0; j < 4; j++)
            #pragma unroll
            for (int t = 0; t < 4; t++) acc[i][j][t] = 0.0f;
}

__device__ __forceinline__ void chunk_mma3(uint32_t base, int wr, int wc, int lane,
                                           float (&acc)[4][4][4])
{
    const int rA = lane & 15, cA = lane >> 4;
    const int rB = (lane & 7) + ((lane >> 4) << 3), cB = (lane >> 3) & 1;
    #pragma unroll
    for (int k16 = 0; k16 < 2; k16++) {
        const int k2 = k16 * 2;
        uint32_t aAddr[4], bAddr[2];
        #pragma unroll
        for (int mi = 0; mi < 4; mi++)
            aAddr[mi] = base + (uint32_t)((wr * 64 + mi * 16 + rA) * ROWB + (k2 + cA) * 16);
        #pragma unroll
        for (int ni = 0; ni < 2; ni++)
            bAddr[ni] = base + 2 * HALFB +
                        (uint32_t)((wc * 32 + ni * 16 + rB) * ROWB + (k2 + cB) * 16);

        uint32_t fAh[4][4], fB[2][4];
        #pragma unroll
        for (int mi = 0; mi < 4; mi++) ldm4(fAh[mi], aAddr[mi]);
        #pragma unroll
        for (int ni = 0; ni < 2; ni++) ldm4(fB[ni], bAddr[ni]);
        #pragma unroll
        for (int mi = 0; mi < 4; mi++)
            #pragma unroll
            for (int nj = 0; nj < 4; nj++) {
                const int bi = nj >> 1, bs = (nj & 1) * 2;
                mma16816(acc[mi][nj], fAh[mi], fB[bi][bs], fB[bi][bs + 1]);
            }
        {
            uint32_t fAl[4][4];
            #pragma unroll
            for (int mi = 0; mi < 4; mi++) ldm4(fAl[mi], aAddr[mi] + HALFB);
            #pragma unroll
            for (int mi = 0; mi < 4; mi++)
                #pragma unroll
                for (int nj = 0; nj < 4; nj++) {
                    const int bi = nj >> 1, bs = (nj & 1) * 2;
                    mma16816(acc[mi][nj], fAl[mi], fB[bi][bs], fB[bi][bs + 1]);
                }
        }
        #pragma unroll
        for (int ni = 0; ni < 2; ni++) ldm4(fB[ni], bAddr[ni] + HALFB);
        #pragma unroll
        for (int mi = 0; mi < 4; mi++)
            #pragma unroll
            for (int nj = 0; nj < 4; nj++) {
                const int bi = nj >> 1, bs = (nj & 1) * 2;
                mma16816(acc[mi][nj], fAh[mi], fB[bi][bs], fB[bi][bs + 1]);
            }
    }
}

// bf16 3-term GEMM (double-buffered pipeline)
__device__ __forceinline__ void gemm_core(
    uint32_t sb, int tid,
    const __nv_bfloat16* __restrict__ Ah, const __nv_bfloat16* __restrict__ Al, int lda,
    const __nv_bfloat16* __restrict__ Bh, const __nv_bfloat16* __restrict__ Bl, int ldb,
    int K, int nvalid, float (&acc)[4][4][4])
{
    const int lane = tid & 31, wid = tid >> 5;
    const int wr = wid >> 2, wc = wid & 3;
    const int nc = K >> 5;

    auto issue = [&](int st, int c) {
        #pragma unroll
        for (int j = 0; j < 2; j++) {
            int id = tid + j * 256;
            int row = id >> 2, ch = id & 3;
            long long offa = (long long)row * lda + c * 32 + ch * 8;
            uint32_t d = sb + st * STAGEB + row * ROWB + ch * 16;
            cp16(d,         Ah + offa, 16);
            cp16(d + HALFB, Al + offa, 16);
            long long offb = (long long)row * ldb + c * 32 + ch * 8;
            int vb = (row < nvalid) ? 16 : 0;
            if (vb == 0) offb = 0;
            cp16(d + 2 * HALFB, Bh + offb, vb);
            cp16(d + 3 * HALFB, Bl + offb, vb);
        }
    };

    zero_acc(acc);
    issue(0, 0);
    cp_commit();

    for (int c = 0; c < nc; c++) {
        cp_wait0();
        __syncthreads();
        int nxt = c + 1;
        if (nxt < nc) issue(nxt & 1, nxt);
        cp_commit();
        chunk_mma3(sb + (c & 1) * STAGEB, wr, wc, lane, acc);
    }
    __syncthreads();
}

// fp16 2-term GEMM core (A hi-only, B hi+lo), 2-stage double buffer (proven R8 core)
#define STAGEB2 30720
#define GSMEM2  (2 * STAGEB2)

__device__ __forceinline__ void gemm_core_f16(
    uint32_t sb, int tid,
    const __half* __restrict__ Ah, int lda,
    const __half* __restrict__ Bh, const __half* __restrict__ Bl, int ldb,
    int K, float (&acc)[4][4][4])
{
    const int lane = tid & 31, wid = tid >> 5;
    const int wr = wid >> 2, wc = wid & 3;
    const int nc = K >> 5;

    auto issue = [&](int st, int c) {
        #pragma unroll
        for (int j = 0; j < 2; j++) {
            int id = tid + j * 256;
            int row = id >> 2, ch = id & 3;
            long long offa = (long long)row * lda + c * 32 + ch * 8;
            uint32_t d = sb + st * STAGEB2 + row * ROWB + ch * 16;
            cp16(d, Ah + offa, 16);
            long long offb = (long long)row * ldb + c * 32 + ch * 8;
            cp16(d + HALFB,     Bh + offb, 16);
            cp16(d + 2 * HALFB, Bl + offb, 16);
        }
    };

    zero_acc(acc);
    issue(0, 0);
    cp_commit();

    const int rA = lane & 15, cA = lane >> 4;
    const int rB = (lane & 7) + ((lane >> 4) << 3), cB = (lane >> 3) & 1;

    for (int c = 0; c < nc; c++) {
        cp_wait0();
        __syncthreads();
        int nxt = c + 1;
        if (nxt < nc) issue(nxt & 1, nxt);
        cp_commit();
        const uint32_t base = sb + (c & 1) * STAGEB2;
        #pragma unroll
        for (int k16 = 0; k16 < 2; k16++) {
            const int k2 = k16 * 2;
            uint32_t aAddr[4], bAddr[2];
            #pragma unroll
            for (int mi = 0; mi < 4; mi++)
                aAddr[mi] = base + (uint32_t)((wr * 64 + mi * 16 + rA) * ROWB + (k2 + cA) * 16);
            #pragma unroll
            for (int ni = 0; ni < 2; ni++)
                bAddr[ni] = base + HALFB +
                            (uint32_t)((wc * 32 + ni * 16 + rB) * ROWB + (k2 + cB) * 16);

            uint32_t fAh[4][4], fB[2][4];
            #pragma unroll
            for (int mi = 0; mi < 4; mi++) ldm4(fAh[mi], aAddr[mi]);
            #pragma unroll
            for (int ni = 0; ni < 2; ni++) ldm4(fB[ni], bAddr[ni]);
            #pragma unroll
            for (int mi = 0; mi < 4; mi++)
                #pragma unroll
                for (int nj = 0; nj < 4; nj++) {
                    const int bi = nj >> 1, bs = (nj & 1) * 2;
                    mma16816h(acc[mi][nj], fAh[mi], fB[bi][bs], fB[bi][bs + 1]);
                }
            #pragma unroll
            for (int ni = 0; ni < 2; ni++) ldm4(fB[ni], bAddr[ni] + HALFB);
            #pragma unroll
            for (int mi = 0; mi < 4; mi++)
                #pragma unroll
                for (int nj = 0; nj < 4; nj++) {
                    const int bi = nj >> 1, bs = (nj & 1) * 2;
                    mma16816h(acc[mi][nj], fAh[mi], fB[bi][bs], fB[bi][bs + 1]);
                }
        }
    }
    __syncthreads();
}

// ---------------- epilogues ----------------
__device__ __forceinline__ void epi_bias(float (&acc)[4][4][4], const float* bias,
                                         int blockCol, int wc, int lane) {
    #pragma unroll
    for (int nj = 0; nj < 4; nj++) {
        const int col = blockCol + wc * 32 + nj * 8 + (lane & 3) * 2;
        float b0 = bias[col], b1 = bias[col + 1];
        #pragma unroll
        for (int mi = 0; mi < 4; mi++) {
            acc[mi][nj][0] += b0; acc[mi][nj][1] += b1;
            acc[mi][nj][2] += b0; acc[mi][nj][3] += b1;
        }
    }
}

__device__ __forceinline__ void epi_split_store(
    float (&acc)[4][4][4], __nv_bfloat16* Ch, __nv_bfloat16* Cl, int ldc,
    int blockRow, int blockCol, int ncols, int wr, int wc, int lane)
{
    #pragma unroll
    for (int mi = 0; mi < 4; mi++) {
        long long R0 = (long long)(blockRow + wr * 64 + mi * 16 + (lane >> 2)) * ldc;
        long long R1 = R0 + 8LL * ldc;
        #pragma unroll
        for (int nj = 0; nj < 4; nj++) {
            int col = blockCol + wc * 32 + nj * 8 + (lane & 3) * 2;
            if (col >= ncols) continue;
            spair(Ch, Cl, R0 + col, acc[mi][nj][0], acc[mi][nj][1]);
            spair(Ch, Cl, R1 + col, acc[mi][nj][2], acc[mi][nj][3]);
        }
    }
}

__device__ __forceinline__ void epi_split_store_f16(
    float (&acc)[4][4][4], __half* Ch, __half* Cl, int ldc,
    int blockRow, int blockCol, int ncols, int wr, int wc, int lane)
{
    #pragma unroll
    for (int mi = 0; mi < 4; mi++) {
        long long R0 = (long long)(blockRow + wr * 64 + mi * 16 + (lane >> 2)) * ldc;
        long long R1 = R0 + 8LL * ldc;
        #pragma unroll
        for (int nj = 0; nj < 4; nj++) {
            int col = blockCol + wc * 32 + nj * 8 + (lane & 3) * 2;
            if (col >= ncols) continue;
            spair_f16(Ch, Cl, R0 + col, acc[mi][nj][0], acc[mi][nj][1]);
            spair_f16(Ch, Cl, R1 + col, acc[mi][nj][2], acc[mi][nj][3]);
        }
    }
}

__device__ __forceinline__ void epi_f32_store(
    float (&acc)[4][4][4], float* Cf, int ldc,
    int blockRow, int blockCol, int wr, int wc, int lane)
{
    #pragma unroll
    for (int mi = 0; mi < 4; mi++) {
        long long R0 = (long long)(blockRow + wr * 64 + mi * 16 + (lane >> 2)) * ldc;
        long long R1 = R0 + 8LL * ldc;
        #pragma unroll
        for (int nj = 0; nj < 4; nj++) {
            int col = blockCol + wc * 32 + nj * 8 + (lane & 3) * 2;
            *(float2*)(Cf + R0 + col) = make_float2(acc[mi][nj][0], acc[mi][nj][1]);
            *(float2*)(Cf + R1 + col) = make_float2(acc[mi][nj][2], acc[mi][nj][3]);
        }
    }
}

// fused 112-slot softmax + fp16 store
__device__ __forceinline__ void softmax_store(
    float (&acc)[4][4][4], float* sred, float* ssum, const float (&scl)[4][2],
    __half* Ch, int ldc, int blockRow, bool write_pads, int wr, int wc, int lane)
{
    #pragma unroll
    for (int mi = 0; mi < 4; mi++) {
        float m0 = -1e30f, m1 = -1e30f;
        #pragma unroll
        for (int nj = 0; nj < 4; nj++) {
            const int col = wc * 32 + nj * 8 + (lane & 3) * 2;
            bool ok = col < SLOT;
            float l0 = ok ? scl[mi][0] * acc[mi][nj][0] : -1e30f;
            float l1 = ok ? scl[mi][0] * acc[mi][nj][1] : -1e30f;
            float l2 = ok ? scl[mi][1] * acc[mi][nj][2] : -1e30f;
            float l3 = ok ? scl[mi][1] * acc[mi][nj][3] : -1e30f;
            acc[mi][nj][0] = l0; acc[mi][nj][1] = l1;
            acc[mi][nj][2] = l2; acc[mi][nj][3] = l3;
            m0 = fmaxf(m0, fmaxf(l0, l1)); m1 = fmaxf(m1, fmaxf(l2, l3));
        }
        m0 = qred_max(m0); m1 = qred_max(m1);
        if ((lane & 3) == 0) {
            int r0 = wr * 64 + mi * 16 + (lane >> 2);
            sred[r0 * 4 + wc] = m0;
            sred[(r0 + 8) * 4 + wc] = m1;
        }
    }
    __syncthreads();
    #pragma unroll
    for (int mi = 0; mi < 4; mi++) {
        int r0 = wr * 64 + mi * 16 + (lane >> 2), r1 = r0 + 8;
        float M0 = fmaxf(fmaxf(sred[r0 * 4], sred[r0 * 4 + 1]),
                         fmaxf(sred[r0 * 4 + 2], sred[r0 * 4 + 3]));
        float M1 = fmaxf(fmaxf(sred[r1 * 4], sred[r1 * 4 + 1]),
                         fmaxf(sred[r1 * 4 + 2], sred[r1 * 4 + 3]));
        float s0 = 0.f, s1 = 0.f;
        #pragma unroll
        for (int nj = 0; nj < 4; nj++) {
            const int col = wc * 32 + nj * 8 + (lane & 3) * 2;
            bool ok = col < SLOT;
            float e0 = ok ? __expf(acc[mi][nj][0] - M0) : 0.f;
            float e1 = ok ? __expf(acc[mi][nj][1] - M0) : 0.f;
            float e2 = ok ? __expf(acc[mi][nj][2] - M1) : 0.f;
            float e3 = ok ? __expf(acc[mi][nj][3] - M1) : 0.f;
            acc[mi][nj][0] = e0; acc[mi][nj][1] = e1;
            acc[mi][nj][2] = e2; acc[mi][nj][3] = e3;
            s0 += e0 + e1; s1 += e2 + e3;
        }
        s0 = qred_sum(s0); s1 = qred_sum(s1);
        if ((lane & 3) == 0) {
            ssum[r0 * 4 + wc] = s0;
            ssum[r1 * 4 + wc] = s1;
        }
    }
    __syncthreads();
    #pragma unroll
    for (int mi = 0; mi < 4; mi++) {
        int r0l = wr * 64 + mi * 16 + (lane >> 2), r1l = r0l + 8;
        float i0 = 1.0f / (ssum[r0l * 4] + ssum[r0l * 4 + 1] + ssum[r0l * 4 + 2] + ssum[r0l * 4 + 3]);
        float i1 = 1.0f / (ssum[r1l * 4] + ssum[r1l * 4 + 1] + ssum[r1l * 4 + 2] + ssum[r1l * 4 + 3]);
        long long R0 = (long long)(blockRow + r0l) * ldc;
        long long R1 = (long long)(blockRow + r1l) * ldc;
        #pragma unroll
        for (int nj = 0; nj < 4; nj++) {
            const int col = wc * 32 + nj * 8 + (lane & 3) * 2;
            if (!write_pads && col >= SLOT) continue;
            hpair(Ch, R0 + col, acc[mi][nj][0] * i0, acc[mi][nj][1] * i0);
            hpair(Ch, R1 + col, acc[mi][nj][2] * i1, acc[mi][nj][3] * i1);
        }
    }
}

// ---------------- stage 1: eq (z=0), ev (z=1), m2t (z=2) ----------------
__global__ void __launch_bounds__(256, 2) gemm_stage1(
    const __nv_bfloat16* __restrict__ q_h, const __nv_bfloat16* __restrict__ q_l,
    const __nv_bfloat16* __restrict__ wq_h, const __nv_bfloat16* __restrict__ wq_l,
    const __nv_bfloat16* __restrict__ v_h, const __nv_bfloat16* __restrict__ v_l,
    const __nv_bfloat16* __restrict__ wv_h, const __nv_bfloat16* __restrict__ wv_l,
    const __nv_bfloat16* __restrict__ wl_h, const __nv_bfloat16* __restrict__ wl_l,
    const __nv_bfloat16* __restrict__ vm_h, const __nv_bfloat16* __restrict__ vm_l,
    __nv_bfloat16* eqn_h, __nv_bfloat16* eqn_l,
    __nv_bfloat16* ev_h, __nv_bfloat16* ev_l,
    __half* m2h, __half* m2l,
    const float* __restrict__ bq, const float* __restrict__ bv,
    float* __restrict__ invkn, float* __restrict__ gpart)
{
    extern __shared__ char smem[];
    const uint32_t sb = smem_u32(smem);
    const int tid = threadIdx.x, lane = tid & 31, wid = tid >> 5;
    const int wr = wid >> 2, wc = wid & 3;
    const int z = blockIdx.z;
    float acc[4][4][4];

    if (z == 2) {
        if (blockIdx.x != 0 || blockIdx.y >= 32) return;
        int h = blockIdx.y & 7, mb = blockIdx.y >> 3;
        gemm_core(sb, tid, wl_h + h * 512 + (long long)mb * 128 * (HEAD * DIM),
                  wl_l + h * 512 + (long long)mb * 128 * (HEAD * DIM), HEAD * DIM,
                  vm_h, vm_l, DIM, DIM, SLOT, acc);
        epi_split_store_f16(acc, m2h + h * SLOT, m2l + h * SLOT, HEAD * SLOT,
                            mb * 128, 0, SLOT, wr, wc, lane);
        return;
    }

    const int blockRow = blockIdx.y * 128, blockCol = blockIdx.x * 128;
    if (z == 0)
        gemm_core(sb, tid, q_h + (long long)blockRow * DIM, q_l + (long long)blockRow * DIM, DIM,
                  wq_h + (long long)blockCol * DIM, wq_l + (long long)blockCol * DIM, DIM,
                  DIM, 128, acc);
    else
        gemm_core(sb, tid, v_h + (long long)blockRow * DIM, v_l + (long long)blockRow * DIM, DIM,
                  wv_h + (long long)blockCol * DIM, wv_l + (long long)blockCol * DIM, DIM,
                  DIM, 128, acc);

    epi_bias(acc, z == 0 ? bq : bv, blockCol, wc, lane);

    float* sred = (float*)smem;
    #pragma unroll
    for (int mi = 0; mi < 4; mi++) {
        float s0 = 0.f, s1 = 0.f;
        #pragma unroll
        for (int nj = 0; nj < 4; nj++) {
            s0 += acc[mi][nj][0] * acc[mi][nj][0] + acc[mi][nj][1] * acc[mi][nj][1];
            s1 += acc[mi][nj][2] * acc[mi][nj][2] + acc[mi][nj][3] * acc[mi][nj][3];
        }
        s0 = qred_sum(s0); s1 = qred_sum(s1);
        if ((lane & 3) == 0) {
            int r0 = wr * 64 + mi * 16 + (lane >> 2);
            sred[r0 * 4 + wc] = s0;
            sred[(r0 + 8) * 4 + wc] = s1;
        }
    }
    __syncthreads();
    if (z == 0) {
        if ((wc == 0 || wc == 2) && (lane & 3) == 0) {
            #pragma unroll
            for (int mi = 0; mi < 4; mi++)
                #pragma unroll
                for (int half = 0; half < 2; half++) {
                    int r = wr * 64 + mi * 16 + (lane >> 2) + half * 8;
                    float s = sred[r * 4 + wc] + sred[r * 4 + wc + 1];
                    invkn[(long long)(blockRow + r) * HEAD + blockIdx.x * 2 + (wc >> 1)]
                        = 1.0f / fmaxf(sqrtf(s), 1e-12f);
                }
        }
    } else {
        if (wc == 0 && (lane & 3) == 0) {
            #pragma unroll
            for (int mi = 0; mi < 4; mi++)
                #pragma unroll
                for (int half = 0; half < 2; half++) {
                    int r = wr * 64 + mi * 16 + (lane >> 2) + half * 8;
                    float s = sred[r * 4] + sred[r * 4 + 1] + sred[r * 4 + 2] + sred[r * 4 + 3];
                    gpart[(long long)(blockRow + r) * 4 + blockIdx.x] = s;
                }
        }
    }
    epi_split_store(acc, z == 0 ? eqn_h : ev_h, z == 0 ? eqn_l : ev_l, DIM,
                    blockRow, blockCol, 1 << 30, wr, wc, lane);
}

// ---------------- stage 2: vsim (z=0) + ksim heads (z=1..8) ----------------
__global__ void __launch_bounds__(256, 2) gemm_sim(
    const __nv_bfloat16* __restrict__ eqn_h, const __nv_bfloat16* __restrict__ eqn_l,
    const __nv_bfloat16* __restrict__ kn_h, const __nv_bfloat16* __restrict__ kn_l,
    const __nv_bfloat16* __restrict__ ev_h, const __nv_bfloat16* __restrict__ ev_l,
    const __nv_bfloat16* __restrict__ vn_h, const __nv_bfloat16* __restrict__ vn_l,
    __half* ka, __half* va,
    const float* __restrict__ invkn, const float* __restrict__ gpart)
{
    extern __shared__ char smem[];
    const uint32_t sb = smem_u32(smem);
    float* sredE = (float*)(smem + 2 * STAGEB);
    float* ssumE = sredE + 512;
    const int tid = threadIdx.x, lane = tid & 31, wid = tid >> 5;
    const int wr = wid >> 2, wc = wid & 3;
    const int z = blockIdx.z;
    const int blockRow = blockIdx.y * 128;
    float acc[4][4][4];

    __half* Ch;
    int ldc;
    bool is_val = (z == 0);
    if (is_val) {
        gemm_core(sb, tid, ev_h + (long long)blockRow * DIM, ev_l + (long long)blockRow * DIM, DIM,
                  vn_h, vn_l, DIM, DIM, SLOT, acc);
        Ch = va; ldc = 128;
    } else {
        int h = z - 1;
        gemm_core(sb, tid, eqn_h + (long long)blockRow * DIM + h * HD,
                  eqn_l + (long long)blockRow * DIM + h * HD, DIM,
                  kn_h + (long long)h * SLOT * HD, kn_l + (long long)h * SLOT * HD, HD,
                  HD, SLOT, acc);
        Ch = ka + h * SLOT; ldc = HEAD * SLOT;
    }

    const int h = z - 1;
    float scl[4][2];
    #pragma unroll
    for (int mi = 0; mi < 4; mi++)
        #pragma unroll
        for (int half = 0; half < 2; half++) {
            int r = blockRow + wr * 64 + mi * 16 + (lane >> 2) + half * 8;
            float iv;
            if (is_val) {
                float s4 = gpart[r * 4] + gpart[r * 4 + 1] + gpart[r * 4 + 2] + gpart[r * 4 + 3];
                iv = 1.0f / fmaxf(sqrtf(s4), 1e-12f);
            } else {
                iv = invkn[(long long)r * HEAD + h];
            }
            scl[mi][half] = RADIUSF * iv;
        }
    softmax_store(acc, sredE, ssumE, scl, Ch, ldc, blockRow, is_val, wr, wc, lane);
}

// ---------------- stage 3 (fp16 2-term): virpre (z=0, K=896) + aud (z=1, K=128) ----------------
__global__ void __launch_bounds__(256, 2) gemm_out(
    const __half* __restrict__ ka, const __half* __restrict__ m2h, const __half* __restrict__ m2l,
    const __half* __restrict__ va, const __half* __restrict__ vth, const __half* __restrict__ vtl,
    float* __restrict__ virpre, float* __restrict__ aud,
    const float* __restrict__ bl)
{
    extern __shared__ char smem[];
    const uint32_t sb = smem_u32(smem);
    const int tid = threadIdx.x, lane = tid & 31, wid = tid >> 5;
    const int wr = wid >> 2, wc = wid & 3;
    const int z = blockIdx.z;
    const int blockRow = blockIdx.y * 128, blockCol = blockIdx.x * 128;
    float acc[4][4][4];

    if (z == 0) {
        gemm_core_f16(sb, tid, ka + (long long)blockRow * (HEAD * SLOT), HEAD * SLOT,
                      m2h + (long long)blockCol * (HEAD * SLOT),
                      m2l + (long long)blockCol * (HEAD * SLOT), HEAD * SLOT,
                      HEAD * SLOT, acc);
        epi_bias(acc, bl, blockCol, wc, lane);
        epi_f32_store(acc, virpre, DIM, blockRow, blockCol, wr, wc, lane);
    } else {
        gemm_core_f16(sb, tid, va + (long long)blockRow * 128, 128,
                      vth + (long long)blockCol * 128,
                      vtl + (long long)blockCol * 128, 128,
                      128, acc);
        epi_f32_store(acc, aud, DIM, blockRow, blockCol, wr, wc, lane);
    }
}

// ---------------- mega prep (coarsened: 2 float4/thread in split sections) ----------------
#define NB_Q  4096
#define NB_V  4096
#define NB_WQ 128
#define NB_WV 128
#define NB_WL 1024
#define NB_VM 28
#define NB_KN 112
#define NB_VN 112
#define NB_VT 256
#define NB_CP 112
#define NB_TOTAL (NB_Q+NB_V+NB_WQ+NB_WV+NB_WL+NB_VM+NB_KN+NB_VN+NB_VT+NB_CP)

__device__ __forceinline__ void do_split4(const float4* src, __nv_bfloat16* h,
                                          __nv_bfloat16* l, long long i) {
    float4 v = src[i];
    __nv_bfloat16 h0 = __float2bfloat16_rn(v.x), h1 = __float2bfloat16_rn(v.y);
    __nv_bfloat16 h2 = __float2bfloat16_rn(v.z), h3 = __float2bfloat16_rn(v.w);
    *(__nv_bfloat162*)(h + i * 4)     = __halves2bfloat162(h0, h1);
    *(__nv_bfloat162*)(h + i * 4 + 2) = __halves2bfloat162(h2, h3);
    *(__nv_bfloat162*)(l + i * 4) = __halves2bfloat162(
        __float2bfloat16_rn(v.x - __bfloat162float(h0)),
        __float2bfloat16_rn(v.y - __bfloat162float(h1)));
    *(__nv_bfloat162*)(l + i * 4 + 2) = __halves2bfloat162(
        __float2bfloat16_rn(v.z - __bfloat162float(h2)),
        __float2bfloat16_rn(v.w - __bfloat162float(h3)));
}
__device__ __forceinline__ void do_split8(const float4* src, __nv_bfloat16* h,
                                          __nv_bfloat16* l, long long b, int tid) {
    do_split4(src, h, l, b * 512 + tid);
    do_split4(src, h, l, b * 512 + 256 + tid);
}

__global__ void mega_prep(
    const float* __restrict__ query, const float* __restrict__ value,
    const float* __restrict__ key_mem, const float* __restrict__ value_mem,
    const float* __restrict__ Wq, const float* __restrict__ Wv, const float* __restrict__ Wl,
    __nv_bfloat16* q_h, __nv_bfloat16* q_l, __nv_bfloat16* v_h, __nv_bfloat16* v_l,
    __nv_bfloat16* wq_h, __nv_bfloat16* wq_l, __nv_bfloat16* wv_h, __nv_bfloat16* wv_l,
    __nv_bfloat16* wl_h, __nv_bfloat16* wl_l, __nv_bfloat16* vm_h, __nv_bfloat16* vm_l,
    __nv_bfloat16* kn_h, __nv_bfloat16* kn_l, __nv_bfloat16* vn_h, __nv_bfloat16* vn_l,
    __half* vth, __half* vtl, float* cpart)
{
    __shared__ float sh[544];
    int b = blockIdx.x, tid = threadIdx.x;

    if (b < NB_Q) { do_split8((const float4*)query, q_h, q_l, b, tid); return; }
    b -= NB_Q;
    if (b < NB_V) { do_split8((const float4*)value, v_h, v_l, b, tid); return; }
    b -= NB_V;
    if (b < NB_WQ) { do_split8((const float4*)Wq, wq_h, wq_l, b, tid); return; }
    b -= NB_WQ;
    if (b < NB_WV) { do_split8((const float4*)Wv, wv_h, wv_l, b, tid); return; }
    b -= NB_WV;
    if (b < NB_WL) { do_split8((const float4*)Wl, wl_h, wl_l, b, tid); return; }
    b -= NB_WL;
    if (b < NB_VM) { do_split8((const float4*)value_mem, vm_h, vm_l, b, tid); return; }
    b -= NB_VM;
    if (b < NB_KN) {
        int seg = b * 8 + (tid >> 5), lane = tid & 31;
        long long base = (long long)seg * 64;
        float a = key_mem[base + lane], c = key_mem[base + lane + 32];
        float s = a * a + c * c;
        #pragma unroll
        for (int o = 16; o; o >>= 1) s += __shfl_xor_sync(0xffffffffu, s, o);
        float inv = 1.0f / fmaxf(sqrtf(s), 1e-12f);
        wsplit(kn_h, kn_l, base + lane, a * inv);
        wsplit(kn_h, kn_l, base + lane + 32, c * inv);
        return;
    }
    b -= NB_KN;
    if (b < NB_VN) {
        long long r = b;
        float a = value_mem[r * DIM + tid], c = value_mem[r * DIM + tid + 256];
        float s = blockReduceSum(a * a + c * c, sh);
        float inv = 1.0f / fmaxf(sqrtf(s), 1e-12f);
        wsplit(vn_h, vn_l, r * DIM + tid, a * inv);
        wsplit(vn_h, vn_l, r * DIM + tid + 256, c * inv);
        return;
    }
    b -= NB_VN;
    if (b < NB_VT) {
        int idx = b * 256 + tid;
        int j = idx >> 7, s = idx & 127;
        float v = (s < SLOT) ? value_mem[(long long)s * DIM + j] : 0.0f;
        wsplit_f16(vth, vtl, idx, v);
        return;
    }
    b -= NB_VT;
    {
        int i = b;
        float* vi = sh;
        float* red = sh + 512;
        for (int c = tid; c < DIM; c += 256) vi[c] = value_mem[(long long)i * DIM + c];
        __syncthreads();
        float s = 0.f;
        for (int c = tid; c < DIM; c += 256) s += vi[c] * vi[c];
        s = blockReduceSum(s, red);
        float ni = fmaxf(sqrtf(s), 1e-12f);
        int w = tid >> 5, lane = tid & 31;
        float acc = 0.f;
        for (int j = w; j < SLOT; j += 8) {
            float d = 0.f, jj = 0.f;
            for (int c = lane; c < DIM; c += 32) {
                float vj = value_mem[(long long)j * DIM + c];
                d += vi[c] * vj; jj += vj * vj;
            }
            #pragma unroll
            for (int o = 16; o; o >>= 1) {
                d += __shfl_down_sync(0xffffffffu, d, o);
                jj += __shfl_down_sync(0xffffffffu, jj, o);
            }
            if (lane == 0) {
                float nj = fmaxf(sqrtf(jj), 1e-12f);
                acc += fabsf(((i == j) ? 1.0f : 0.0f) - d / (ni * nj));
            }
        }
        acc = blockReduceSum(acc, red);
        if (tid == 0) cpart[i] = acc;
    }
}

// ---------------- fused te+tr layernorm (dual-value single-sync reductions) ----------------
__global__ void fuse_tetr(const float* __restrict__ virpre, const float* __restrict__ aud,
                          const float* __restrict__ query, const float* __restrict__ value,
                          const float* __restrict__ g1, const float* __restrict__ b1,
                          const float* __restrict__ g2, const float* __restrict__ b2,
                          const float* __restrict__ g3, const float* __restrict__ b3,
                          float* __restrict__ out_te, float* __restrict__ out_tr,
                          float* __restrict__ cosbuf)
{
    __shared__ float red[24];     // 3 rotating regions x 8 floats
    bool is_tr = blockIdx.x >= NROWS;
    long long r = is_tr ? (blockIdx.x - NROWS) : blockIdx.x;
    const float* src = (is_tr ? aud : virpre) + r * DIM;
    const float* q = query + r * DIM;
    const float* gx = is_tr ? g3 : g2;
    const float* bx = is_tr ? b3 : b2;
    float* o = (is_tr ? out_tr : out_te) + r * DIM;

    float x[4], qv[4];
    float s = 0.f, s2 = 0.f;
    #pragma unroll
    for (int i = 0; i < 4; i++) {
        int c = threadIdx.x + 128 * i;
        x[i] = src[c]; qv[i] = q[c];
        s += x[i]; s2 += x[i] * x[i];
    }
    blockReduceSum2_128(s, s2, red);          // region 0
    if (is_tr) {
        const float* v = value + r * DIM;
        float sav = 0.f, svv = 0.f;
        #pragma unroll
        for (int i = 0; i < 4; i++) {
            int c = threadIdx.x + 128 * i;
            float vv = v[c];
            sav += x[i] * vv; svv += vv * vv;
        }
        blockReduceSum2_128(sav, svv, red + 8);  // region 1
        if (threadIdx.x == 0) {
            float cosv = sav / fmaxf(sqrtf(s2) * sqrtf(svv), 1e-8f);
            cosbuf[r] = fabsf(1.0f - cosv);
        }
    }
    float mu = s * (1.0f / DIM);
    float var = s2 * (1.0f / DIM) - mu * mu;
    float inv = rsqrtf(var + 1e-5f);
    float t[4]; float ts = 0.f, ts2 = 0.f;
    #pragma unroll
    for (int i = 0; i < 4; i++) {
        int c = threadIdx.x + 128 * i;
        float ln = (x[i] - mu) * inv * gx[c] + bx[c];
        t[i] = qv[i] + ln; ts += t[i]; ts2 += t[i] * t[i];
    }
    blockReduceSum2_128(ts, ts2, red + 16);   // region 2
    mu = ts * (1.0f / DIM);
    var = ts2 * (1.0f / DIM) - mu * mu;
    inv = rsqrtf(var + 1e-5f);
    #pragma unroll
    for (int i = 0; i < 4; i++) {
        int c = threadIdx.x + 128 * i;
        o[c] = (t[i] - mu) * inv * g1[c] + b1[c];
    }
}

// ---------------- final reductions ----------------
__global__ void final_reduce(const float* __restrict__ cosbuf, const float* __restrict__ cpart,
                             float* __restrict__ recon, float* __restrict__ contr)
{
    __shared__ float red[32];
    int b = blockIdx.x;
    if (b < 32) {
        float s = 0.0f;
        for (int i = threadIdx.x; i < 512; i += blockDim.x) s += cosbuf[b * 512 + i];
        s = blockReduceSum(s, red);
        if (threadIdx.x == 0) recon[b] = s;
    } else {
        float s = 0.0f;
        for (int i = threadIdx.x; i < SLOT; i += blockDim.x) s += cpart[i];
        s = blockReduceSum(s, red);
        if (threadIdx.x == 0) contr[0] = 0.5f * s;
    }
}

// ---------------- launch ----------------
#define SYM(p, s) cudaGetSymbolAddress((void**)&p, s)

extern "C" void kernel_launch(void* const* d_in, const int* in_sizes, int n_in,
                              void* d_out, int out_size)
{
    const float* query     = (const float*)d_in[0];
    const float* value     = (const float*)d_in[1];
    const float* key_mem   = (const float*)d_in[2];
    const float* value_mem = (const float*)d_in[3];
    const float* Wq = (const float*)d_in[4];
    const float* bq = (const float*)d_in[5];
    const float* Wv = (const float*)d_in[6];
    const float* bv = (const float*)d_in[7];
    const float* Wl = (const float*)d_in[8];
    const float* bl = (const float*)d_in[9];
    const float* g1 = (const float*)d_in[10];
    const float* b1 = (const float*)d_in[11];
    const float* g2 = (const float*)d_in[12];
    const float* b2 = (const float*)d_in[13];
    const float* g3 = (const float*)d_in[14];
    const float* b3 = (const float*)d_in[15];

    float* out        = (float*)d_out;
    float* out_te     = out;
    float* out_tr     = out + (long long)NROWS * DIM;
    float* out_recon  = out + 2ll * NROWS * DIM;
    float* out_contr  = out_recon + 32;

    float *p_virpre, *p_aud, *p_invkn, *p_gpart, *p_cos, *p_cpart;
    SYM(p_virpre, g_virpre); SYM(p_aud, g_aud);
    SYM(p_invkn, g_invkn); SYM(p_gpart, g_gpart);
    SYM(p_cos, g_cosbuf); SYM(p_cpart, g_cpart);

    __nv_bfloat16 *q_h, *q_l, *v_h, *v_l, *wq_h, *wq_l, *wv_h, *wv_l, *wl_h, *wl_l;
    __nv_bfloat16 *vm_h, *vm_l, *eqn_h, *eqn_l, *kn_h, *kn_l;
    __nv_bfloat16 *ev_h, *ev_l, *vn_h, *vn_l;
    __half *ka, *va, *m2h, *m2l, *vth, *vtl;
    SYM(q_h, g_q_h); SYM(q_l, g_q_l); SYM(v_h, g_v_h); SYM(v_l, g_v_l);
    SYM(wq_h, g_wq_h); SYM(wq_l, g_wq_l); SYM(wv_h, g_wv_h); SYM(wv_l, g_wv_l);
    SYM(wl_h, g_wl_h); SYM(wl_l, g_wl_l); SYM(vm_h, g_vm_h); SYM(vm_l, g_vm_l);
    SYM(eqn_h, g_eqn_h); SYM(eqn_l, g_eqn_l); SYM(kn_h, g_kn_h); SYM(kn_l, g_kn_l);
    SYM(ev_h, g_ev_h); SYM(ev_l, g_ev_l); SYM(vn_h, g_vn_h); SYM(vn_l, g_vn_l);
    SYM(ka, g_ka); SYM(va, g_va); SYM(m2h, g_m2h); SYM(m2l, g_m2l);
    SYM(vth, g_vth); SYM(vtl, g_vtl);

    cudaFuncSetAttribute(gemm_stage1, cudaFuncAttributeMaxDynamicSharedMemorySize, GSMEM);
    cudaFuncSetAttribute(gemm_sim,    cudaFuncAttributeMaxDynamicSharedMemorySize, GSMEM_SIM);
    cudaFuncSetAttribute(gemm_out,    cudaFuncAttributeMaxDynamicSharedMemorySize, GSMEM2);

    // 0: all prep (splits, norms, contrastive partials)
    mega_prep<<<NB_TOTAL, 256>>>(query, value, key_mem, value_mem, Wq, Wv, Wl,
                                 q_h, q_l, v_h, v_l, wq_h, wq_l, wv_h, wv_l,
                                 wl_h, wl_l, vm_h, vm_l, kn_h, kn_l, vn_h, vn_l,
                                 vth, vtl, p_cpart);

    // 1: eq (z=0) + ev (z=1) + m2t (z=2, fp16 split out)
    gemm_stage1<<<dim3(4, 128, 3), 256, GSMEM>>>(
        q_h, q_l, wq_h, wq_l, v_h, v_l, wv_h, wv_l, wl_h, wl_l, vm_h, vm_l,
        eqn_h, eqn_l, ev_h, ev_l, m2h, m2l, bq, bv, p_invkn, p_gpart);

    // 2: vsim (z=0) + ksim heads (z=1..8), fused softmaxes -> fp16
    gemm_sim<<<dim3(1, 128, 9), 256, GSMEM_SIM>>>(
        eqn_h, eqn_l, kn_h, kn_l, ev_h, ev_l, vn_h, vn_l,
        ka, va, p_invkn, p_gpart);

    // 3: virpre (z=0, K=896) + aud (z=1, K=128) — fp16 2-term, 2-stage (proven)
    gemm_out<<<dim3(4, 128, 2), 256, GSMEM2>>>(
        ka, m2h, m2l, va, vth, vtl, p_virpre, p_aud, bl);

    // 4: fused te + tr double-layernorm (+cos), reduced barrier count
    fuse_tetr<<<2 * NROWS, 128>>>(p_virpre, p_aud, query, value,
                                  g1, b1, g2, b2, g3, b3, out_te, out_tr, p_cos);

    // 5: recon per-batch sums + contrastive final
    final_reduce<<<33, 128>>>(p_cos, p_cpart, out_recon, out_contr);
}

// round 14
// speedup vs baseline: 1.1974x; 1.0350x over previous
#include <cuda_runtime.h>
#include <cuda_bf16.h>
#include <cuda_fp16.h>
#include <cstdint>

#define NROWS 16384   // B*S
#define DIM 512
#define HEAD 8
#define SLOT 112
#define HD 64
#define RADIUSF 16.0f

// ---------------- scratch (device globals) ----------------
__device__ float g_virpre[NROWS * DIM];
__device__ float g_aud[NROWS * DIM];
__device__ float g_invkn[NROWS * HEAD];
__device__ float g_gpart[NROWS * 4];
__device__ float g_cosbuf[NROWS];
__device__ float g_cpart[SLOT];
// bf16 split pairs (softmax-feeding path: 3-term accuracy)
__device__ __nv_bfloat16 g_q_h[NROWS * DIM],  g_q_l[NROWS * DIM];
__device__ __nv_bfloat16 g_v_h[NROWS * DIM],  g_v_l[NROWS * DIM];
__device__ __nv_bfloat16 g_wq_h[DIM * DIM],   g_wq_l[DIM * DIM];
__device__ __nv_bfloat16 g_wv_h[DIM * DIM],   g_wv_l[DIM * DIM];
__device__ __nv_bfloat16 g_wl_h[DIM * DIM * HEAD], g_wl_l[DIM * DIM * HEAD];
__device__ __nv_bfloat16 g_vm_h[SLOT * DIM],  g_vm_l[SLOT * DIM];
__device__ __nv_bfloat16 g_eqn_h[NROWS * DIM], g_eqn_l[NROWS * DIM];
__device__ __nv_bfloat16 g_kn_h[HEAD * SLOT * HD], g_kn_l[HEAD * SLOT * HD];
__device__ __nv_bfloat16 g_ev_h[NROWS * DIM], g_ev_l[NROWS * DIM];
__device__ __nv_bfloat16 g_vn_h[SLOT * DIM],  g_vn_l[SLOT * DIM];
// fp16 post-softmax operands.
// ka/va are FRAGMENT BLOBS: per 16x16 tile, 32 lanes x 4 half2 (16B/lane), tile = 512B.
// ka: 1024 row-tiles x 56 col-tiles; va: 1024 row-tiles x 8 col-tiles.
__device__ __half g_ka[NROWS * HEAD * SLOT];
__device__ __half g_va[NROWS * 128];
__device__ __half g_m2h[DIM * HEAD * SLOT], g_m2l[DIM * HEAD * SLOT];
__device__ __half g_vth[DIM * 128],         g_vtl[DIM * 128];

// ---------------- helpers ----------------
__device__ __forceinline__ uint32_t smem_u32(const void* p) {
    uint32_t a;
    asm("{ .reg .u64 t; cvta.to.shared.u64 t, %1; cvt.u32.u64 %0, t; }" : "=r"(a) : "l"(p));
    return a;
}
__device__ __forceinline__ void cp16(uint32_t dst, const void* src, int sz) {
    asm volatile("cp.async.cg.shared.global [%0], [%1], 16, %2;"
                 :: "r"(dst), "l"(src), "r"(sz));
}
__device__ __forceinline__ void cp_commit() { asm volatile("cp.async.commit_group;" ::: "memory"); }
__device__ __forceinline__ void cp_wait0()  { asm volatile("cp.async.wait_group 0;"  ::: "memory"); }

__device__ __forceinline__ void ldm4(uint32_t (&r)[4], uint32_t a) {
    asm volatile("ldmatrix.sync.aligned.m8n8.x4.shared.b16 {%0,%1,%2,%3}, [%4];"
                 : "=r"(r[0]), "=r"(r[1]), "=r"(r[2]), "=r"(r[3]) : "r"(a));
}
__device__ __forceinline__ void mma16816(float (&c)[4], const uint32_t (&a)[4],
                                         uint32_t b0, uint32_t b1) {
    asm volatile(
        "mma.sync.aligned.m16n8k16.row.col.f32.bf16.bf16.f32 "
        "{%0,%1,%2,%3}, {%4,%5,%6,%7}, {%8,%9}, {%0,%1,%2,%3};"
        : "+f"(c[0]), "+f"(c[1]), "+f"(c[2]), "+f"(c[3])
        : "r"(a[0]), "r"(a[1]), "r"(a[2]), "r"(a[3]), "r"(b0), "r"(b1));
}
__device__ __forceinline__ void mma16816h4(float (&c)[4], uint4 a,
                                           uint32_t b0, uint32_t b1) {
    asm volatile(
        "mma.sync.aligned.m16n8k16.row.col.f32.f16.f16.f32 "
        "{%0,%1,%2,%3}, {%4,%5,%6,%7}, {%8,%9}, {%0,%1,%2,%3};"
        : "+f"(c[0]), "+f"(c[1]), "+f"(c[2]), "+f"(c[3])
        : "r"(a.x), "r"(a.y), "r"(a.z), "r"(a.w), "r"(b0), "r"(b1));
}
__device__ __forceinline__ void wsplit(__nv_bfloat16* h, __nv_bfloat16* l, long long i, float v) {
    __nv_bfloat16 hh = __float2bfloat16_rn(v);
    h[i] = hh;
    l[i] = __float2bfloat16_rn(v - __bfloat162float(hh));
}
__device__ __forceinline__ void wsplit_f16(__half* h, __half* l, long long i, float v) {
    __half hh = __float2half_rn(v);
    h[i] = hh;
    l[i] = __float2half_rn(v - __half2float(hh));
}
__device__ __forceinline__ void spair(__nv_bfloat16* H, __nv_bfloat16* L, long long i,
                                      float a, float b) {
    __nv_bfloat16 h0 = __float2bfloat16_rn(a), h1 = __float2bfloat16_rn(b);
    *(__nv_bfloat162*)(H + i) = __halves2bfloat162(h0, h1);
    *(__nv_bfloat162*)(L + i) = __halves2bfloat162(
        __float2bfloat16_rn(a - __bfloat162float(h0)),
        __float2bfloat16_rn(b - __bfloat162float(h1)));
}
__device__ __forceinline__ void spair_f16(__half* H, __half* L, long long i,
                                          float a, float b) {
    __half h0 = __float2half_rn(a), h1 = __float2half_rn(b);
    *(__half2*)(H + i) = __halves2half2(h0, h1);
    *(__half2*)(L + i) = __halves2half2(
        __float2half_rn(a - __half2float(h0)),
        __float2half_rn(b - __half2float(h1)));
}
__device__ __forceinline__ uint32_t pack_h2(float a, float b) {
    __half2 h = __floats2half2_rn(a, b);
    return *(uint32_t*)&h;
}
__device__ __forceinline__ float qred_sum(float v) {
    v += __shfl_xor_sync(0xffffffffu, v, 1);
    v += __shfl_xor_sync(0xffffffffu, v, 2);
    return v;
}
__device__ __forceinline__ float qred_max(float v) {
    v = fmaxf(v, __shfl_xor_sync(0xffffffffu, v, 1));
    v = fmaxf(v, __shfl_xor_sync(0xffffffffu, v, 2));
    return v;
}
__device__ __forceinline__ float blockReduceSum(float v, float* red) {
    int lane = threadIdx.x & 31, w = threadIdx.x >> 5;
    #pragma unroll
    for (int o = 16; o; o >>= 1) v += __shfl_down_sync(0xffffffffu, v, o);
    if (lane == 0) red[w] = v;
    __syncthreads();
    int nw = blockDim.x >> 5;
    float r = (threadIdx.x < nw) ? red[threadIdx.x] : 0.0f;
    if (w == 0) {
        #pragma unroll
        for (int o = 16; o; o >>= 1) r += __shfl_down_sync(0xffffffffu, r, o);
        if (lane == 0) red[0] = r;
    }
    __syncthreads();
    float out = red[0];
    __syncthreads();
    return out;
}
__device__ __forceinline__ void blockReduceSum2_128(float& a, float& b, float* red) {
    int lane = threadIdx.x & 31, w = threadIdx.x >> 5;
    #pragma unroll
    for (int o = 16; o; o >>= 1) {
        a += __shfl_down_sync(0xffffffffu, a, o);
        b += __shfl_down_sync(0xffffffffu, b, o);
    }
    if (lane == 0) { red[w] = a; red[4 + w] = b; }
    __syncthreads();
    a = red[0] + red[1] + red[2] + red[3];
    b = red[4] + red[5] + red[6] + red[7];
}

// ---------------- GEMM building blocks ----------------
#define ROWB   80
#define HALFB  10240
#define STAGEB 40960
#define GSMEM     (2 * STAGEB)
#define GSMEM_SIM (2 * STAGEB + 4096)

__device__ __forceinline__ void zero_acc(float (&acc)[4][4][4]) {
    #pragma unroll
    for (int i = 0; i < 4; i++)
        #pragma unroll
        for (int j = 0; j < 4; j++)
            #pragma unroll
            for (int t = 0; t < 4; t++) acc[i][j][t] = 0.0f;
}

__device__ __forceinline__ void chunk_mma3(uint32_t base, int wr, int wc, int lane,
                                           float (&acc)[4][4][4])
{
    const int rA = lane & 15, cA = lane >> 4;
    const int rB = (lane & 7) + ((lane >> 4) << 3), cB = (lane >> 3) & 1;
    #pragma unroll
    for (int k16 = 0; k16 < 2; k16++) {
        const int k2 = k16 * 2;
        uint32_t aAddr[4], bAddr[2];
        #pragma unroll
        for (int mi = 0; mi < 4; mi++)
            aAddr[mi] = base + (uint32_t)((wr * 64 + mi * 16 + rA) * ROWB + (k2 + cA) * 16);
        #pragma unroll
        for (int ni = 0; ni < 2; ni++)
            bAddr[ni] = base + 2 * HALFB +
                        (uint32_t)((wc * 32 + ni * 16 + rB) * ROWB + (k2 + cB) * 16);

        uint32_t fAh[4][4], fB[2][4];
        #pragma unroll
        for (int mi = 0; mi < 4; mi++) ldm4(fAh[mi], aAddr[mi]);
        #pragma unroll
        for (int ni = 0; ni < 2; ni++) ldm4(fB[ni], bAddr[ni]);
        #pragma unroll
        for (int mi = 0; mi < 4; mi++)
            #pragma unroll
            for (int nj = 0; nj < 4; nj++) {
                const int bi = nj >> 1, bs = (nj & 1) * 2;
                mma16816(acc[mi][nj], fAh[mi], fB[bi][bs], fB[bi][bs + 1]);
            }
        {
            uint32_t fAl[4][4];
            #pragma unroll
            for (int mi = 0; mi < 4; mi++) ldm4(fAl[mi], aAddr[mi] + HALFB);
            #pragma unroll
            for (int mi = 0; mi < 4; mi++)
                #pragma unroll
                for (int nj = 0; nj < 4; nj++) {
                    const int bi = nj >> 1, bs = (nj & 1) * 2;
                    mma16816(acc[mi][nj], fAl[mi], fB[bi][bs], fB[bi][bs + 1]);
                }
        }
        #pragma unroll
        for (int ni = 0; ni < 2; ni++) ldm4(fB[ni], bAddr[ni] + HALFB);
        #pragma unroll
        for (int mi = 0; mi < 4; mi++)
            #pragma unroll
            for (int nj = 0; nj < 4; nj++) {
                const int bi = nj >> 1, bs = (nj & 1) * 2;
                mma16816(acc[mi][nj], fAh[mi], fB[bi][bs], fB[bi][bs + 1]);
            }
    }
}

// bf16 3-term GEMM (double-buffered pipeline)
__device__ __forceinline__ void gemm_core(
    uint32_t sb, int tid,
    const __nv_bfloat16* __restrict__ Ah, const __nv_bfloat16* __restrict__ Al, int lda,
    const __nv_bfloat16* __restrict__ Bh, const __nv_bfloat16* __restrict__ Bl, int ldb,
    int K, int nvalid, float (&acc)[4][4][4])
{
    const int lane = tid & 31, wid = tid >> 5;
    const int wr = wid >> 2, wc = wid & 3;
    const int nc = K >> 5;

    auto issue = [&](int st, int c) {
        #pragma unroll
        for (int j = 0; j < 2; j++) {
            int id = tid + j * 256;
            int row = id >> 2, ch = id & 3;
            long long offa = (long long)row * lda + c * 32 + ch * 8;
            uint32_t d = sb + st * STAGEB + row * ROWB + ch * 16;
            cp16(d,         Ah + offa, 16);
            cp16(d + HALFB, Al + offa, 16);
            long long offb = (long long)row * ldb + c * 32 + ch * 8;
            int vb = (row < nvalid) ? 16 : 0;
            if (vb == 0) offb = 0;
            cp16(d + 2 * HALFB, Bh + offb, vb);
            cp16(d + 3 * HALFB, Bl + offb, vb);
        }
    };

    zero_acc(acc);
    issue(0, 0);
    cp_commit();

    for (int c = 0; c < nc; c++) {
        cp_wait0();
        __syncthreads();
        int nxt = c + 1;
        if (nxt < nc) issue(nxt & 1, nxt);
        cp_commit();
        chunk_mma3(sb + (c & 1) * STAGEB, wr, wc, lane, acc);
    }
    __syncthreads();
}

// fp16 2-term GEMM core: A from fragment blob via LDG.128, B (hi+lo) via cp.async+ldmatrix
#define HALFB2  10240
#define STAGEB3 20480
#define GSMEM2  (2 * STAGEB3)

__device__ __forceinline__ void gemm_core_f16_blob(
    uint32_t sb, int tid,
    const __half* __restrict__ Ablob, int nct, int rtBase,
    const __half* __restrict__ Bh, const __half* __restrict__ Bl, int ldb,
    int K, float (&acc)[4][4][4])
{
    const int lane = tid & 31, wid = tid >> 5;
    const int wr = wid >> 2, wc = wid & 3;
    const int nc = K >> 5;

    // fill full 64B/row for both Bh and Bl: 512 segments each (2 iters x 256 threads)
    auto issue = [&](int st, int c) {
        #pragma unroll
        for (int j = 0; j < 2; j++) {
            int id = tid + j * 256;
            int row = id >> 2, ch = id & 3;
            long long offb = (long long)row * ldb + c * 32 + ch * 8;
            uint32_t d = sb + st * STAGEB3 + row * ROWB + ch * 16;
            cp16(d,          Bh + offb, 16);
            cp16(d + HALFB2, Bl + offb, 16);
        }
    };

    zero_acc(acc);
    issue(0, 0);
    cp_commit();

    const int rB = (lane & 7) + ((lane >> 4) << 3), cB = (lane >> 3) & 1;
    const long long rt0 = (long long)(rtBase + wr * 4);

    for (int c = 0; c < nc; c++) {
        cp_wait0();
        __syncthreads();
        int nxt = c + 1;
        if (nxt < nc) issue(nxt & 1, nxt);
        cp_commit();
        const uint32_t base = sb + (c & 1) * STAGEB3;

        // A fragments for both k16 halves: 8 coalesced LDG.128
        uint4 q[2][4];
        #pragma unroll
        for (int k16 = 0; k16 < 2; k16++)
            #pragma unroll
            for (int mi = 0; mi < 4; mi++)
                q[k16][mi] = *(const uint4*)(Ablob +
                    ((rt0 + mi) * nct + (2 * c + k16)) * 256 + lane * 8);

        #pragma unroll
        for (int k16 = 0; k16 < 2; k16++) {
            const int k2 = k16 * 2;
            uint32_t bAddr[2];
            #pragma unroll
            for (int ni = 0; ni < 2; ni++)
                bAddr[ni] = base +
                    (uint32_t)((wc * 32 + ni * 16 + rB) * ROWB + (k2 + cB) * 16);

            uint32_t fB[2][4];
            #pragma unroll
            for (int ni = 0; ni < 2; ni++) ldm4(fB[ni], bAddr[ni]);
            #pragma unroll
            for (int mi = 0; mi < 4; mi++)
                #pragma unroll
                for (int nj = 0; nj < 4; nj++) {
                    const int bi = nj >> 1, bs = (nj & 1) * 2;
                    mma16816h4(acc[mi][nj], q[k16][mi], fB[bi][bs], fB[bi][bs + 1]);
                }
            #pragma unroll
            for (int ni = 0; ni < 2; ni++) ldm4(fB[ni], bAddr[ni] + HALFB2);
            #pragma unroll
            for (int mi = 0; mi < 4; mi++)
                #pragma unroll
                for (int nj = 0; nj < 4; nj++) {
                    const int bi = nj >> 1, bs = (nj & 1) * 2;
                    mma16816h4(acc[mi][nj], q[k16][mi], fB[bi][bs], fB[bi][bs + 1]);
                }
        }
    }
    __syncthreads();
}

// ---------------- epilogues ----------------
__device__ __forceinline__ void epi_bias(float (&acc)[4][4][4], const float* bias,
                                         int blockCol, int wc, int lane) {
    #pragma unroll
    for (int nj = 0; nj < 4; nj++) {
        const int col = blockCol + wc * 32 + nj * 8 + (lane & 3) * 2;
        float b0 = bias[col], b1 = bias[col + 1];
        #pragma unroll
        for (int mi = 0; mi < 4; mi++) {
            acc[mi][nj][0] += b0; acc[mi][nj][1] += b1;
            acc[mi][nj][2] += b0; acc[mi][nj][3] += b1;
        }
    }
}

__device__ __forceinline__ void epi_split_store(
    float (&acc)[4][4][4], __nv_bfloat16* Ch, __nv_bfloat16* Cl, int ldc,
    int blockRow, int blockCol, int ncols, int wr, int wc, int lane)
{
    #pragma unroll
    for (int mi = 0; mi < 4; mi++) {
        long long R0 = (long long)(blockRow + wr * 64 + mi * 16 + (lane >> 2)) * ldc;
        long long R1 = R0 + 8LL * ldc;
        #pragma unroll
        for (int nj = 0; nj < 4; nj++) {
            int col = blockCol + wc * 32 + nj * 8 + (lane & 3) * 2;
            if (col >= ncols) continue;
            spair(Ch, Cl, R0 + col, acc[mi][nj][0], acc[mi][nj][1]);
            spair(Ch, Cl, R1 + col, acc[mi][nj][2], acc[mi][nj][3]);
        }
    }
}

__device__ __forceinline__ void epi_split_store_f16(
    float (&acc)[4][4][4], __half* Ch, __half* Cl, int ldc,
    int blockRow, int blockCol, int ncols, int wr, int wc, int lane)
{
    #pragma unroll
    for (int mi = 0; mi < 4; mi++) {
        long long R0 = (long long)(blockRow + wr * 64 + mi * 16 + (lane >> 2)) * ldc;
        long long R1 = R0 + 8LL * ldc;
        #pragma unroll
        for (int nj = 0; nj < 4; nj++) {
            int col = blockCol + wc * 32 + nj * 8 + (lane & 3) * 2;
            if (col >= ncols) continue;
            spair_f16(Ch, Cl, R0 + col, acc[mi][nj][0], acc[mi][nj][1]);
            spair_f16(Ch, Cl, R1 + col, acc[mi][nj][2], acc[mi][nj][3]);
        }
    }
}

__device__ __forceinline__ void epi_f32_store(
    float (&acc)[4][4][4], float* Cf, int ldc,
    int blockRow, int blockCol, int wr, int wc, int lane)
{
    #pragma unroll
    for (int mi = 0; mi < 4; mi++) {
        long long R0 = (long long)(blockRow + wr * 64 + mi * 16 + (lane >> 2)) * ldc;
        long long R1 = R0 + 8LL * ldc;
        #pragma unroll
        for (int nj = 0; nj < 4; nj++) {
            int col = blockCol + wc * 32 + nj * 8 + (lane & 3) * 2;
            *(float2*)(Cf + R0 + col) = make_float2(acc[mi][nj][0], acc[mi][nj][1]);
            *(float2*)(Cf + R1 + col) = make_float2(acc[mi][nj][2], acc[mi][nj][3]);
        }
    }
}

// fused 112-slot softmax + fragment-blob store (A-operand layout for the out-GEMM).
__device__ __forceinline__ void softmax_store_blob(
    float (&acc)[4][4][4], float* sred, float* ssum, const float (&scl)[4][2],
    __half* blob, int nct, int ct_off, int ct_lim,
    int blockRow, int wr, int wc, int lane)
{
    #pragma unroll
    for (int mi = 0; mi < 4; mi++) {
        float m0 = -1e30f, m1 = -1e30f;
        #pragma unroll
        for (int nj = 0; nj < 4; nj++) {
            const int col = wc * 32 + nj * 8 + (lane & 3) * 2;
            bool ok = col < SLOT;
            float l0 = ok ? scl[mi][0] * acc[mi][nj][0] : -1e30f;
            float l1 = ok ? scl[mi][0] * acc[mi][nj][1] : -1e30f;
            float l2 = ok ? scl[mi][1] * acc[mi][nj][2] : -1e30f;
            float l3 = ok ? scl[mi][1] * acc[mi][nj][3] : -1e30f;
            acc[mi][nj][0] = l0; acc[mi][nj][1] = l1;
            acc[mi][nj][2] = l2; acc[mi][nj][3] = l3;
            m0 = fmaxf(m0, fmaxf(l0, l1)); m1 = fmaxf(m1, fmaxf(l2, l3));
        }
        m0 = qred_max(m0); m1 = qred_max(m1);
        if ((lane & 3) == 0) {
            int r0 = wr * 64 + mi * 16 + (lane >> 2);
            sred[r0 * 4 + wc] = m0;
            sred[(r0 + 8) * 4 + wc] = m1;
        }
    }
    __syncthreads();
    #pragma unroll
    for (int mi = 0; mi < 4; mi++) {
        int r0 = wr * 64 + mi * 16 + (lane >> 2), r1 = r0 + 8;
        float M0 = fmaxf(fmaxf(sred[r0 * 4], sred[r0 * 4 + 1]),
                         fmaxf(sred[r0 * 4 + 2], sred[r0 * 4 + 3]));
        float M1 = fmaxf(fmaxf(sred[r1 * 4], sred[r1 * 4 + 1]),
                         fmaxf(sred[r1 * 4 + 2], sred[r1 * 4 + 3]));
        float s0 = 0.f, s1 = 0.f;
        #pragma unroll
        for (int nj = 0; nj < 4; nj++) {
            const int col = wc * 32 + nj * 8 + (lane & 3) * 2;
            bool ok = col < SLOT;
            float e0 = ok ? __expf(acc[mi][nj][0] - M0) : 0.f;
            float e1 = ok ? __expf(acc[mi][nj][1] - M0) : 0.f;
            float e2 = ok ? __expf(acc[mi][nj][2] - M1) : 0.f;
            float e3 = ok ? __expf(acc[mi][nj][3] - M1) : 0.f;
            acc[mi][nj][0] = e0; acc[mi][nj][1] = e1;
            acc[mi][nj][2] = e2; acc[mi][nj][3] = e3;
            s0 += e0 + e1; s1 += e2 + e3;
        }
        s0 = qred_sum(s0); s1 = qred_sum(s1);
        if ((lane & 3) == 0) {
            ssum[r0 * 4 + wc] = s0;
            ssum[r1 * 4 + wc] = s1;
        }
    }
    __syncthreads();
    #pragma unroll
    for (int mi = 0; mi < 4; mi++) {
        int r0l = wr * 64 + mi * 16 + (lane >> 2), r1l = r0l + 8;
        float i0 = 1.0f / (ssum[r0l * 4] + ssum[r0l * 4 + 1] + ssum[r0l * 4 + 2] + ssum[r0l * 4 + 3]);
        float i1 = 1.0f / (ssum[r1l * 4] + ssum[r1l * 4 + 1] + ssum[r1l * 4 + 2] + ssum[r1l * 4 + 3]);
        long long rt = (blockRow >> 4) + wr * 4 + mi;
        #pragma unroll
        for (int njp = 0; njp < 2; njp++) {
            int ctl = wc * 2 + njp;
            if (ctl >= ct_lim) continue;
            const int e = njp * 2, o = e + 1;
            uint4 w;
            w.x = pack_h2(acc[mi][e][0] * i0, acc[mi][e][1] * i0);
            w.y = pack_h2(acc[mi][e][2] * i1, acc[mi][e][3] * i1);
            w.z = pack_h2(acc[mi][o][0] * i0, acc[mi][o][1] * i0);
            w.w = pack_h2(acc[mi][o][2] * i1, acc[mi][o][3] * i1);
            *(uint4*)(blob + (rt * nct + ct_off + ctl) * 256 + lane * 8) = w;
        }
    }
}

// ---------------- stage 1: eq (z=0), ev (z=1), m2t (z=2) ----------------
__global__ void __launch_bounds__(256, 2) gemm_stage1(
    const __nv_bfloat16* __restrict__ q_h, const __nv_bfloat16* __restrict__ q_l,
    const __nv_bfloat16* __restrict__ wq_h, const __nv_bfloat16* __restrict__ wq_l,
    const __nv_bfloat16* __restrict__ v_h, const __nv_bfloat16* __restrict__ v_l,
    const __nv_bfloat16* __restrict__ wv_h, const __nv_bfloat16* __restrict__ wv_l,
    const __nv_bfloat16* __restrict__ wl_h, const __nv_bfloat16* __restrict__ wl_l,
    const __nv_bfloat16* __restrict__ vm_h, const __nv_bfloat16* __restrict__ vm_l,
    __nv_bfloat16* eqn_h, __nv_bfloat16* eqn_l,
    __nv_bfloat16* ev_h, __nv_bfloat16* ev_l,
    __half* m2h, __half* m2l,
    const float* __restrict__ bq, const float* __restrict__ bv,
    float* __restrict__ invkn, float* __restrict__ gpart)
{
    extern __shared__ char smem[];
    const uint32_t sb = smem_u32(smem);
    const int tid = threadIdx.x, lane = tid & 31, wid = tid >> 5;
    const int wr = wid >> 2, wc = wid & 3;
    const int z = blockIdx.z;
    float acc[4][4][4];

    if (z == 2) {
        if (blockIdx.x != 0 || blockIdx.y >= 32) return;
        int h = blockIdx.y & 7, mb = blockIdx.y >> 3;
        gemm_core(sb, tid, wl_h + h * 512 + (long long)mb * 128 * (HEAD * DIM),
                  wl_l + h * 512 + (long long)mb * 128 * (HEAD * DIM), HEAD * DIM,
                  vm_h, vm_l, DIM, DIM, SLOT, acc);
        epi_split_store_f16(acc, m2h + h * SLOT, m2l + h * SLOT, HEAD * SLOT,
                            mb * 128, 0, SLOT, wr, wc, lane);
        return;
    }

    const int blockRow = blockIdx.y * 128, blockCol = blockIdx.x * 128;
    if (z == 0)
        gemm_core(sb, tid, q_h + (long long)blockRow * DIM, q_l + (long long)blockRow * DIM, DIM,
                  wq_h + (long long)blockCol * DIM, wq_l + (long long)blockCol * DIM, DIM,
                  DIM, 128, acc);
    else
        gemm_core(sb, tid, v_h + (long long)blockRow * DIM, v_l + (long long)blockRow * DIM, DIM,
                  wv_h + (long long)blockCol * DIM, wv_l + (long long)blockCol * DIM, DIM,
                  DIM, 128, acc);

    epi_bias(acc, z == 0 ? bq : bv, blockCol, wc, lane);

    float* sred = (float*)smem;
    #pragma unroll
    for (int mi = 0; mi < 4; mi++) {
        float s0 = 0.f, s1 = 0.f;
        #pragma unroll
        for (int nj = 0; nj < 4; nj++) {
            s0 += acc[mi][nj][0] * acc[mi][nj][0] + acc[mi][nj][1] * acc[mi][nj][1];
            s1 += acc[mi][nj][2] * acc[mi][nj][2] + acc[mi][nj][3] * acc[mi][nj][3];
        }
        s0 = qred_sum(s0); s1 = qred_sum(s1);
        if ((lane & 3) == 0) {
            int r0 = wr * 64 + mi * 16 + (lane >> 2);
            sred[r0 * 4 + wc] = s0;
            sred[(r0 + 8) * 4 + wc] = s1;
        }
    }
    __syncthreads();
    if (z == 0) {
        if ((wc == 0 || wc == 2) && (lane & 3) == 0) {
            #pragma unroll
            for (int mi = 0; mi < 4; mi++)
                #pragma unroll
                for (int half = 0; half < 2; half++) {
                    int r = wr * 64 + mi * 16 + (lane >> 2) + half * 8;
                    float s = sred[r * 4 + wc] + sred[r * 4 + wc + 1];
                    invkn[(long long)(blockRow + r) * HEAD + blockIdx.x * 2 + (wc >> 1)]
                        = 1.0f / fmaxf(sqrtf(s), 1e-12f);
                }
        }
    } else {
        if (wc == 0 && (lane & 3) == 0) {
            #pragma unroll
            for (int mi = 0; mi < 4; mi++)
                #pragma unroll
                for (int half = 0; half < 2; half++) {
                    int r = wr * 64 + mi * 16 + (lane >> 2) + half * 8;
                    float s = sred[r * 4] + sred[r * 4 + 1] + sred[r * 4 + 2] + sred[r * 4 + 3];
                    gpart[(long long)(blockRow + r) * 4 + blockIdx.x] = s;
                }
        }
    }
    epi_split_store(acc, z == 0 ? eqn_h : ev_h, z == 0 ? eqn_l : ev_l, DIM,
                    blockRow, blockCol, 1 << 30, wr, wc, lane);
}

// ---------------- stage 2: vsim (z=0) + ksim heads (z=1..8), blob outputs ----------------
__global__ void __launch_bounds__(256, 2) gemm_sim(
    const __nv_bfloat16* __restrict__ eqn_h, const __nv_bfloat16* __restrict__ eqn_l,
    const __nv_bfloat16* __restrict__ kn_h, const __nv_bfloat16* __restrict__ kn_l,
    const __nv_bfloat16* __restrict__ ev_h, const __nv_bfloat16* __restrict__ ev_l,
    const __nv_bfloat16* __restrict__ vn_h, const __nv_bfloat16* __restrict__ vn_l,
    __half* ka, __half* va,
    const float* __restrict__ invkn, const float* __restrict__ gpart)
{
    extern __shared__ char smem[];
    const uint32_t sb = smem_u32(smem);
    float* sredE = (float*)(smem + 2 * STAGEB);
    float* ssumE = sredE + 512;
    const int tid = threadIdx.x, lane = tid & 31, wid = tid >> 5;
    const int wr = wid >> 2, wc = wid & 3;
    const int z = blockIdx.z;
    const int blockRow = blockIdx.y * 128;
    float acc[4][4][4];

    bool is_val = (z == 0);
    const int h = z - 1;
    if (is_val) {
        gemm_core(sb, tid, ev_h + (long long)blockRow * DIM, ev_l + (long long)blockRow * DIM, DIM,
                  vn_h, vn_l, DIM, DIM, SLOT, acc);
    } else {
        gemm_core(sb, tid, eqn_h + (long long)blockRow * DIM + h * HD,
                  eqn_l + (long long)blockRow * DIM + h * HD, DIM,
                  kn_h + (long long)h * SLOT * HD, kn_l + (long long)h * SLOT * HD, HD,
                  HD, SLOT, acc);
    }

    float scl[4][2];
    #pragma unroll
    for (int mi = 0; mi < 4; mi++)
        #pragma unroll
        for (int half = 0; half < 2; half++) {
            int r = blockRow + wr * 64 + mi * 16 + (lane >> 2) + half * 8;
            float iv;
            if (is_val) {
                float s4 = gpart[r * 4] + gpart[r * 4 + 1] + gpart[r * 4 + 2] + gpart[r * 4 + 3];
                iv = 1.0f / fmaxf(sqrtf(s4), 1e-12f);
            } else {
                iv = invkn[(long long)r * HEAD + h];
            }
            scl[mi][half] = RADIUSF * iv;
        }
    if (is_val)
        softmax_store_blob(acc, sredE, ssumE, scl, va, 8, 0, 8, blockRow, wr, wc, lane);
    else
        softmax_store_blob(acc, sredE, ssumE, scl, ka, 56, h * 7, 7, blockRow, wr, wc, lane);
}

// ---------------- stage 3 (fp16 2-term, A-blob): virpre (z=0, K=896) + aud (z=1, K=128) ----------------
__global__ void __launch_bounds__(256, 2) gemm_out(
    const __half* __restrict__ ka, const __half* __restrict__ m2h, const __half* __restrict__ m2l,
    const __half* __restrict__ va, const __half* __restrict__ vth, const __half* __restrict__ vtl,
    float* __restrict__ virpre, float* __restrict__ aud,
    const float* __restrict__ bl)
{
    extern __shared__ char smem[];
    const uint32_t sb = smem_u32(smem);
    const int tid = threadIdx.x, lane = tid & 31, wid = tid >> 5;
    const int wr = wid >> 2, wc = wid & 3;
    const int z = blockIdx.z;
    const int blockRow = blockIdx.y * 128, blockCol = blockIdx.x * 128;
    const int rtBase = blockIdx.y * 8;
    float acc[4][4][4];

    if (z == 0) {
        gemm_core_f16_blob(sb, tid, ka, 56, rtBase,
                           m2h + (long long)blockCol * (HEAD * SLOT),
                           m2l + (long long)blockCol * (HEAD * SLOT), HEAD * SLOT,
                           HEAD * SLOT, acc);
        epi_bias(acc, bl, blockCol, wc, lane);
        epi_f32_store(acc, virpre, DIM, blockRow, blockCol, wr, wc, lane);
    } else {
        gemm_core_f16_blob(sb, tid, va, 8, rtBase,
                           vth + (long long)blockCol * 128,
                           vtl + (long long)blockCol * 128, 128,
                           128, acc);
        epi_f32_store(acc, aud, DIM, blockRow, blockCol, wr, wc, lane);
    }
}

// ---------------- mega prep (coarsened: 2 float4/thread in split sections) ----------------
#define NB_Q  4096
#define NB_V  4096
#define NB_WQ 128
#define NB_WV 128
#define NB_WL 1024
#define NB_VM 28
#define NB_KN 112
#define NB_VN 112
#define NB_VT 256
#define NB_CP 112
#define NB_TOTAL (NB_Q+NB_V+NB_WQ+NB_WV+NB_WL+NB_VM+NB_KN+NB_VN+NB_VT+NB_CP)

__device__ __forceinline__ void do_split4(const float4* src, __nv_bfloat16* h,
                                          __nv_bfloat16* l, long long i) {
    float4 v = src[i];
    __nv_bfloat16 h0 = __float2bfloat16_rn(v.x), h1 = __float2bfloat16_rn(v.y);
    __nv_bfloat16 h2 = __float2bfloat16_rn(v.z), h3 = __float2bfloat16_rn(v.w);
    *(__nv_bfloat162*)(h + i * 4)     = __halves2bfloat162(h0, h1);
    *(__nv_bfloat162*)(h + i * 4 + 2) = __halves2bfloat162(h2, h3);
    *(__nv_bfloat162*)(l + i * 4) = __halves2bfloat162(
        __float2bfloat16_rn(v.x - __bfloat162float(h0)),
        __float2bfloat16_rn(v.y - __bfloat162float(h1)));
    *(__nv_bfloat162*)(l + i * 4 + 2) = __halves2bfloat162(
        __float2bfloat16_rn(v.z - __bfloat162float(h2)),
        __float2bfloat16_rn(v.w - __bfloat162float(h3)));
}
__device__ __forceinline__ void do_split8(const float4* src, __nv_bfloat16* h,
                                          __nv_bfloat16* l, long long b, int tid) {
    do_split4(src, h, l, b * 512 + tid);
    do_split4(src, h, l, b * 512 + 256 + tid);
}

__global__ void mega_prep(
    const float* __restrict__ query, const float* __restrict__ value,
    const float* __restrict__ key_mem, const float* __restrict__ value_mem,
    const float* __restrict__ Wq, const float* __restrict__ Wv, const float* __restrict__ Wl,
    __nv_bfloat16* q_h, __nv_bfloat16* q_l, __nv_bfloat16* v_h, __nv_bfloat16* v_l,
    __nv_bfloat16* wq_h, __nv_bfloat16* wq_l, __nv_bfloat16* wv_h, __nv_bfloat16* wv_l,
    __nv_bfloat16* wl_h, __nv_bfloat16* wl_l, __nv_bfloat16* vm_h, __nv_bfloat16* vm_l,
    __nv_bfloat16* kn_h, __nv_bfloat16* kn_l, __nv_bfloat16* vn_h, __nv_bfloat16* vn_l,
    __half* vth, __half* vtl, float* cpart)
{
    __shared__ float sh[544];
    int b = blockIdx.x, tid = threadIdx.x;

    if (b < NB_Q) { do_split8((const float4*)query, q_h, q_l, b, tid); return; }
    b -= NB_Q;
    if (b < NB_V) { do_split8((const float4*)value, v_h, v_l, b, tid); return; }
    b -= NB_V;
    if (b < NB_WQ) { do_split8((const float4*)Wq, wq_h, wq_l, b, tid); return; }
    b -= NB_WQ;
    if (b < NB_WV) { do_split8((const float4*)Wv, wv_h, wv_l, b, tid); return; }
    b -= NB_WV;
    if (b < NB_WL) { do_split8((const float4*)Wl, wl_h, wl_l, b, tid); return; }
    b -= NB_WL;
    if (b < NB_VM) { do_split8((const float4*)value_mem, vm_h, vm_l, b, tid); return; }
    b -= NB_VM;
    if (b < NB_KN) {
        int seg = b * 8 + (tid >> 5), lane = tid & 31;
        long long base = (long long)seg * 64;
        float a = key_mem[base + lane], c = key_mem[base + lane + 32];
        float s = a * a + c * c;
        #pragma unroll
        for (int o = 16; o; o >>= 1) s += __shfl_xor_sync(0xffffffffu, s, o);
        float inv = 1.0f / fmaxf(sqrtf(s), 1e-12f);
        wsplit(kn_h, kn_l, base + lane, a * inv);
        wsplit(kn_h, kn_l, base + lane + 32, c * inv);
        return;
    }
    b -= NB_KN;
    if (b < NB_VN) {
        long long r = b;
        float a = value_mem[r * DIM + tid], c = value_mem[r * DIM + tid + 256];
        float s = blockReduceSum(a * a + c * c, sh);
        float inv = 1.0f / fmaxf(sqrtf(s), 1e-12f);
        wsplit(vn_h, vn_l, r * DIM + tid, a * inv);
        wsplit(vn_h, vn_l, r * DIM + tid + 256, c * inv);
        return;
    }
    b -= NB_VN;
    if (b < NB_VT) {
        int idx = b * 256 + tid;
        int j = idx >> 7, s = idx & 127;
        float v = (s < SLOT) ? value_mem[(long long)s * DIM + j] : 0.0f;
        wsplit_f16(vth, vtl, idx, v);
        return;
    }
    b -= NB_VT;
    {
        int i = b;
        float* vi = sh;
        float* red = sh + 512;
        for (int c = tid; c < DIM; c += 256) vi[c] = value_mem[(long long)i * DIM + c];
        __syncthreads();
        float s = 0.f;
        for (int c = tid; c < DIM; c += 256) s += vi[c] * vi[c];
        s = blockReduceSum(s, red);
        float ni = fmaxf(sqrtf(s), 1e-12f);
        int w = tid >> 5, lane = tid & 31;
        float acc = 0.f;
        for (int j = w; j < SLOT; j += 8) {
            float d = 0.f, jj = 0.f;
            for (int c = lane; c < DIM; c += 32) {
                float vj = value_mem[(long long)j * DIM + c];
                d += vi[c] * vj; jj += vj * vj;
            }
            #pragma unroll
            for (int o = 16; o; o >>= 1) {
                d += __shfl_down_sync(0xffffffffu, d, o);
                jj += __shfl_down_sync(0xffffffffu, jj, o);
            }
            if (lane == 0) {
                float nj = fmaxf(sqrtf(jj), 1e-12f);
                acc += fabsf(((i == j) ? 1.0f : 0.0f) - d / (ni * nj));
            }
        }
        acc = blockReduceSum(acc, red);
        if (tid == 0) cpart[i] = acc;
    }
}

// ---------------- fused te+tr layernorm (dual-value single-sync reductions) ----------------
__global__ void fuse_tetr(const float* __restrict__ virpre, const float* __restrict__ aud,
                          const float* __restrict__ query, const float* __restrict__ value,
                          const float* __restrict__ g1, const float* __restrict__ b1,
                          const float* __restrict__ g2, const float* __restrict__ b2,
                          const float* __restrict__ g3, const float* __restrict__ b3,
                          float* __restrict__ out_te, float* __restrict__ out_tr,
                          float* __restrict__ cosbuf)
{
    __shared__ float red[24];
    bool is_tr = blockIdx.x >= NROWS;
    long long r = is_tr ? (blockIdx.x - NROWS) : blockIdx.x;
    const float* src = (is_tr ? aud : virpre) + r * DIM;
    const float* q = query + r * DIM;
    const float* gx = is_tr ? g3 : g2;
    const float* bx = is_tr ? b3 : b2;
    float* o = (is_tr ? out_tr : out_te) + r * DIM;

    float x[4], qv[4];
    float s = 0.f, s2 = 0.f;
    #pragma unroll
    for (int i = 0; i < 4; i++) {
        int c = threadIdx.x + 128 * i;
        x[i] = src[c]; qv[i] = q[c];
        s += x[i]; s2 += x[i] * x[i];
    }
    blockReduceSum2_128(s, s2, red);
    if (is_tr) {
        const float* v = value + r * DIM;
        float sav = 0.f, svv = 0.f;
        #pragma unroll
        for (int i = 0; i < 4; i++) {
            int c = threadIdx.x + 128 * i;
            float vv = v[c];
            sav += x[i] * vv; svv += vv * vv;
        }
        blockReduceSum2_128(sav, svv, red + 8);
        if (threadIdx.x == 0) {
            float cosv = sav / fmaxf(sqrtf(s2) * sqrtf(svv), 1e-8f);
            cosbuf[r] = fabsf(1.0f - cosv);
        }
    }
    float mu = s * (1.0f / DIM);
    float var = s2 * (1.0f / DIM) - mu * mu;
    float inv = rsqrtf(var + 1e-5f);
    float t[4]; float ts = 0.f, ts2 = 0.f;
    #pragma unroll
    for (int i = 0; i < 4; i++) {
        int c = threadIdx.x + 128 * i;
        float ln = (x[i] - mu) * inv * gx[c] + bx[c];
        t[i] = qv[i] + ln; ts += t[i]; ts2 += t[i] * t[i];
    }
    blockReduceSum2_128(ts, ts2, red + 16);
    mu = ts * (1.0f / DIM);
    var = ts2 * (1.0f / DIM) - mu * mu;
    inv = rsqrtf(var + 1e-5f);
    #pragma unroll
    for (int i = 0; i < 4; i++) {
        int c = threadIdx.x + 128 * i;
        o[c] = (t[i] - mu) * inv * g1[c] + b1[c];
    }
}

// ---------------- final reductions ----------------
__global__ void final_reduce(const float* __restrict__ cosbuf, const float* __restrict__ cpart,
                             float* __restrict__ recon, float* __restrict__ contr)
{
    __shared__ float red[32];
    int b = blockIdx.x;
    if (b < 32) {
        float s = 0.0f;
        for (int i = threadIdx.x; i < 512; i += blockDim.x) s += cosbuf[b * 512 + i];
        s = blockReduceSum(s, red);
        if (threadIdx.x == 0) recon[b] = s;
    } else {
        float s = 0.0f;
        for (int i = threadIdx.x; i < SLOT; i += blockDim.x) s += cpart[i];
        s = blockReduceSum(s, red);
        if (threadIdx.x == 0) contr[0] = 0.5f * s;
    }
}

// ---------------- launch ----------------
#define SYM(p, s) cudaGetSymbolAddress((void**)&p, s)

extern "C" void kernel_launch(void* const* d_in, const int* in_sizes, int n_in,
                              void* d_out, int out_size)
{
    const float* query     = (const float*)d_in[0];
    const float* value     = (const float*)d_in[1];
    const float* key_mem   = (const float*)d_in[2];
    const float* value_mem = (const float*)d_in[3];
    const float* Wq = (const float*)d_in[4];
    const float* bq = (const float*)d_in[5];
    const float* Wv = (const float*)d_in[6];
    const float* bv = (const float*)d_in[7];
    const float* Wl = (const float*)d_in[8];
    const float* bl = (const float*)d_in[9];
    const float* g1 = (const float*)d_in[10];
    const float* b1 = (const float*)d_in[11];
    const float* g2 = (const float*)d_in[12];
    const float* b2 = (const float*)d_in[13];
    const float* g3 = (const float*)d_in[14];
    const float* b3 = (const float*)d_in[15];

    float* out        = (float*)d_out;
    float* out_te     = out;
    float* out_tr     = out + (long long)NROWS * DIM;
    float* out_recon  = out + 2ll * NROWS * DIM;
    float* out_contr  = out_recon + 32;

    float *p_virpre, *p_aud, *p_invkn, *p_gpart, *p_cos, *p_cpart;
    SYM(p_virpre, g_virpre); SYM(p_aud, g_aud);
    SYM(p_invkn, g_invkn); SYM(p_gpart, g_gpart);
    SYM(p_cos, g_cosbuf); SYM(p_cpart, g_cpart);

    __nv_bfloat16 *q_h, *q_l, *v_h, *v_l, *wq_h, *wq_l, *wv_h, *wv_l, *wl_h, *wl_l;
    __nv_bfloat16 *vm_h, *vm_l, *eqn_h, *eqn_l, *kn_h, *kn_l;
    __nv_bfloat16 *ev_h, *ev_l, *vn_h, *vn_l;
    __half *ka, *va, *m2h, *m2l, *vth, *vtl;
    SYM(q_h, g_q_h); SYM(q_l, g_q_l); SYM(v_h, g_v_h); SYM(v_l, g_v_l);
    SYM(wq_h, g_wq_h); SYM(wq_l, g_wq_l); SYM(wv_h, g_wv_h); SYM(wv_l, g_wv_l);
    SYM(wl_h, g_wl_h); SYM(wl_l, g_wl_l); SYM(vm_h, g_vm_h); SYM(vm_l, g_vm_l);
    SYM(eqn_h, g_eqn_h); SYM(eqn_l, g_eqn_l); SYM(kn_h, g_kn_h); SYM(kn_l, g_kn_l);
    SYM(ev_h, g_ev_h); SYM(ev_l, g_ev_l); SYM(vn_h, g_vn_h); SYM(vn_l, g_vn_l);
    SYM(ka, g_ka); SYM(va, g_va); SYM(m2h, g_m2h); SYM(m2l, g_m2l);
    SYM(vth, g_vth); SYM(vtl, g_vtl);

    cudaFuncSetAttribute(gemm_stage1, cudaFuncAttributeMaxDynamicSharedMemorySize, GSMEM);
    cudaFuncSetAttribute(gemm_sim,    cudaFuncAttributeMaxDynamicSharedMemorySize, GSMEM_SIM);
    cudaFuncSetAttribute(gemm_out,    cudaFuncAttributeMaxDynamicSharedMemorySize, GSMEM2);

    // 0: all prep (splits, norms, contrastive partials)
    mega_prep<<<NB_TOTAL, 256>>>(query, value, key_mem, value_mem, Wq, Wv, Wl,
                                 q_h, q_l, v_h, v_l, wq_h, wq_l, wv_h, wv_l,
                                 wl_h, wl_l, vm_h, vm_l, kn_h, kn_l, vn_h, vn_l,
                                 vth, vtl, p_cpart);

    // 1: eq (z=0) + ev (z=1) + m2t (z=2, fp16 split out)
    gemm_stage1<<<dim3(4, 128, 3), 256, GSMEM>>>(
        q_h, q_l, wq_h, wq_l, v_h, v_l, wv_h, wv_l, wl_h, wl_l, vm_h, vm_l,
        eqn_h, eqn_l, ev_h, ev_l, m2h, m2l, bq, bv, p_invkn, p_gpart);

    // 2: vsim (z=0) + ksim heads (z=1..8), fused softmaxes -> fragment blobs
    gemm_sim<<<dim3(1, 128, 9), 256, GSMEM_SIM>>>(
        eqn_h, eqn_l, kn_h, kn_l, ev_h, ev_l, vn_h, vn_l,
        ka, va, p_invkn, p_gpart);

    // 3: virpre (z=0, K=896) + aud (z=1, K=128) — fp16 2-term, A from blob (no smem A)
    gemm_out<<<dim3(4, 128, 2), 256, GSMEM2>>>(
        ka, m2h, m2l, va, vth, vtl, p_virpre, p_aud, bl);

    // 4: fused te + tr double-layernorm (+cos)
    fuse_tetr<<<2 * NROWS, 128>>>(p_virpre, p_aud, query, value,
                                  g1, b1, g2, b2, g3, b3, out_te, out_tr, p_cos);

    // 5: recon per-batch sums + contrastive final
    final_reduce<<<33, 128>>>(p_cos, p_cpart, out_recon, out_contr);
}